// round 14
// baseline (speedup 1.0000x reference)
#include <cuda_runtime.h>
#include <cuda_bf16.h>
#include <cstdint>
#include <cstddef>

// ---------------------------------------------------------------------------
// Scratch (static __device__ arrays; no allocation anywhere)
// ---------------------------------------------------------------------------
__device__ float g_q [4096 * 1024];
__device__ float g_k [2048 * 1024];
__device__ float g_v [4096 * 1024];
__device__ float g_xm[4096 * 1024];     // x + attn proj (residual mid)
__device__ float g_h1[4096 * 4096];     // FFN pre-gate (w1 out), fp32

// bf16 hi/lo pool: for each tensor, [hi | lo] contiguous
#define SZ_1M  1048576
#define SZ_2M  2097152
#define SZ_4M  4194304
#define SZ_16M 16777216
#define O_WQ 0
#define O_WK (O_WQ + 2 * SZ_1M)
#define O_WV (O_WK + 2 * SZ_1M)
#define O_PW (O_WV + 2 * SZ_1M)
#define O_W1 (O_PW + 2 * SZ_1M)
#define O_W2 (O_W1 + 2 * SZ_4M)
#define O_W3 (O_W2 + 2 * SZ_4M)
#define O_PE (O_W3 + 2 * SZ_4M)
#define O_XN (O_PE + 2 * SZ_2M)
#define O_AT (O_XN + 2 * SZ_4M)
#define O_H  (O_AT + 2 * SZ_4M)
#define BF_TOTAL (O_H + 2 * SZ_16M)
__device__ __nv_bfloat16 g_bf[BF_TOTAL];

// ---------------------------------------------------------------------------
// f32x2 packed helpers (attention path)
// ---------------------------------------------------------------------------
__device__ __forceinline__ unsigned long long pk2(float lo, float hi) {
    unsigned long long r;
    asm("mov.b64 %0, {%1, %2};" : "=l"(r) : "f"(lo), "f"(hi));
    return r;
}
__device__ __forceinline__ float2 upk2(unsigned long long v) {
    float2 r;
    asm("mov.b64 {%0, %1}, %2;" : "=f"(r.x), "=f"(r.y) : "l"(v));
    return r;
}
__device__ __forceinline__ void ffma2(unsigned long long& c, unsigned long long a,
                                      unsigned long long b) {
    asm("fma.rn.f32x2 %0, %1, %2, %0;" : "+l"(c) : "l"(a), "l"(b));
}
__device__ __forceinline__ unsigned long long mul2(unsigned long long a,
                                                   unsigned long long b) {
    unsigned long long r;
    asm("mul.rn.f32x2 %0, %1, %2;" : "=l"(r) : "l"(a), "l"(b));
    return r;
}

__device__ __forceinline__ float siluf(float z) { return z / (1.0f + expf(-z)); }

// write 2 consecutive values as bf16 hi/lo
__device__ __forceinline__ void wr_hilo2(__nv_bfloat16* H, __nv_bfloat16* L,
                                         size_t p, float a, float b) {
    __nv_bfloat16 ha = __float2bfloat16(a), hb = __float2bfloat16(b);
    __nv_bfloat16 la = __float2bfloat16(a - __bfloat162float(ha));
    __nv_bfloat16 lb = __float2bfloat16(b - __bfloat162float(hb));
    *(uint32_t*)(H + p) = (uint32_t)__bfloat16_as_ushort(ha) |
                          ((uint32_t)__bfloat16_as_ushort(hb) << 16);
    *(uint32_t*)(L + p) = (uint32_t)__bfloat16_as_ushort(la) |
                          ((uint32_t)__bfloat16_as_ushort(lb) << 16);
}
// write 4 consecutive values as bf16 hi/lo (8B stores)
__device__ __forceinline__ void wr_hilo4(__nv_bfloat16* H, __nv_bfloat16* L,
                                         size_t p, float4 v) {
    __nv_bfloat16 h0 = __float2bfloat16(v.x), h1 = __float2bfloat16(v.y),
                  h2 = __float2bfloat16(v.z), h3 = __float2bfloat16(v.w);
    __nv_bfloat16 l0 = __float2bfloat16(v.x - __bfloat162float(h0));
    __nv_bfloat16 l1 = __float2bfloat16(v.y - __bfloat162float(h1));
    __nv_bfloat16 l2 = __float2bfloat16(v.z - __bfloat162float(h2));
    __nv_bfloat16 l3 = __float2bfloat16(v.w - __bfloat162float(h3));
    uint2 hp, lp;
    hp.x = (uint32_t)__bfloat16_as_ushort(h0) | ((uint32_t)__bfloat16_as_ushort(h1) << 16);
    hp.y = (uint32_t)__bfloat16_as_ushort(h2) | ((uint32_t)__bfloat16_as_ushort(h3) << 16);
    lp.x = (uint32_t)__bfloat16_as_ushort(l0) | ((uint32_t)__bfloat16_as_ushort(l1) << 16);
    lp.y = (uint32_t)__bfloat16_as_ushort(l2) | ((uint32_t)__bfloat16_as_ushort(l3) << 16);
    *(uint2*)(H + p) = hp;
    *(uint2*)(L + p) = lp;
}

// ---------------------------------------------------------------------------
// mma.sync / ldmatrix / cp.async helpers (plain sm_103-legal PTX)
// ---------------------------------------------------------------------------
__device__ __forceinline__ uint32_t smem_u32(const void* p) {
    uint32_t a;
    asm("{ .reg .u64 t; cvta.to.shared.u64 t, %1; cvt.u32.u64 %0, t; }"
        : "=r"(a) : "l"(p));
    return a;
}
__device__ __forceinline__ void ldmx4(uint32_t* r, uint32_t addr) {
    asm volatile("ldmatrix.sync.aligned.m8n8.x4.shared.b16 {%0,%1,%2,%3}, [%4];"
                 : "=r"(r[0]), "=r"(r[1]), "=r"(r[2]), "=r"(r[3]) : "r"(addr));
}
__device__ __forceinline__ void mma16816(float* d, const uint32_t* a,
                                         const uint32_t* b) {
    asm volatile(
        "mma.sync.aligned.m16n8k16.row.col.f32.bf16.bf16.f32 "
        "{%0,%1,%2,%3}, {%4,%5,%6,%7}, {%8,%9}, {%0,%1,%2,%3};"
        : "+f"(d[0]), "+f"(d[1]), "+f"(d[2]), "+f"(d[3])
        : "r"(a[0]), "r"(a[1]), "r"(a[2]), "r"(a[3]), "r"(b[0]), "r"(b[1]));
}
__device__ __forceinline__ void cp16(uint32_t dst, const void* src) {
    asm volatile("cp.async.cg.shared.global [%0], [%1], 16;"
                 :: "r"(dst), "l"(src) : "memory");
}
__device__ __forceinline__ void cp_commit() {
    asm volatile("cp.async.commit_group;" ::: "memory");
}
__device__ __forceinline__ void cp_wait0() {
    asm volatile("cp.async.wait_group 0;" ::: "memory");
}
__device__ __forceinline__ void cp_wait1() {
    asm volatile("cp.async.wait_group 1;" ::: "memory");
}

// ---------------------------------------------------------------------------
// Tensor-core GEMM v5: C[M,N] = A[M,K]*B[N,K]^T, bf16 hi/lo operands in GMEM.
// 3-term: Ah*Bh + Ah*Bl + Al*Bh (rel err ~2^-17).
// 128x128x32 tile, 512 threads = 16 warps (4x4), warp tile 32x32.
// smem row = 128B [hi 64B | lo 64B], 16B chunks xor-swizzled by (row&3)
// (2-way ldmatrix bank conflict accepted; LDS is not the bottleneck).
// 3-stage cp.async pipeline. 96KB smem/CTA -> TWO CTAs per SM (8 warps/SMSP)
// so barrier stalls of one CTA overlap the other's MMA stream.
// EPI: 0 fp32 store | 1 res+acc+bias fp32 | 2 acc+bias fp32
//      3 silu(res)*(acc+bias) -> bf16 hi/lo outputs
// ---------------------------------------------------------------------------
#define MBM 128
#define MBN 128
#define MBK 32
#define STAGE 32768               // A 16KB + B 16KB (hi+lo)
#define NSTAGE 3
#define MM_SMEM (NSTAGE * STAGE)

template <int EPI>
__global__ __launch_bounds__(512, 2)
void mma_gemm(const __nv_bfloat16* __restrict__ Ah, const __nv_bfloat16* __restrict__ Al,
              const __nv_bfloat16* __restrict__ Bh, const __nv_bfloat16* __restrict__ Bl,
              const float* __restrict__ bias, const float* __restrict__ res,
              float* __restrict__ C, __nv_bfloat16* __restrict__ Oh,
              __nv_bfloat16* __restrict__ Ol, int M, int N, int K)
{
    extern __shared__ char smem[];
    const uint32_t smem_b = smem_u32(smem);
    const int tid = threadIdx.x;
    const int wid = tid >> 5;
    const int lid = tid & 31;
    const int warp_m = wid >> 2;          // 0..3
    const int warp_n = wid & 3;           // 0..3
    const int bm = blockIdx.y * MBM;
    const int bn = blockIdx.x * MBN;

    const int g   = lid >> 2;             // groupID 0..7
    const int tig = lid & 3;
    const int mat = lid >> 3;             // ldmatrix matrix id 0..3
    const int rwi = lid & 7;

    const int rowA_base = warp_m * 32 + rwi + (mat & 1) * 8;   // + am*16
    const int khA       = mat >> 1;       // k16-half within chunk
    const int rowB_base = warp_n * 32 + (mat >> 1) * 8 + rwi;  // + pr*16
    const int khB       = mat & 1;

    float acc[2][4][4];
#pragma unroll
    for (int i = 0; i < 2; ++i)
#pragma unroll
        for (int j = 0; j < 4; ++j)
#pragma unroll
            for (int q = 0; q < 4; ++q) acc[i][j][q] = 0.0f;

    const __nv_bfloat16* Ahb = Ah + (size_t)bm * K;
    const __nv_bfloat16* Alb = Al + (size_t)bm * K;
    const __nv_bfloat16* Bhb = Bh + (size_t)bn * K;
    const __nv_bfloat16* Blb = Bl + (size_t)bn * K;
    const int nchunks = K / MBK;

    // cp.async loader: 512 threads, 4 x 16B each (Ah, Al, Bh, Bl)
    const int lrow = tid >> 2;            // 0..127
    const int lch  = tid & 3;             // 0..3 (16B chunk within 64B half)

    auto issue = [&](int kc, int stage) {
        const uint32_t sb2 = smem_b + stage * STAGE;
        const size_t koff = (size_t)kc * MBK + lch * 8;
        const uint32_t sw16 = (uint32_t)(((lch ^ (lrow & 3)) << 4));
        cp16(sb2 + lrow * 128 + sw16,              Ahb + (size_t)lrow * K + koff);
        cp16(sb2 + lrow * 128 + 64 + sw16,         Alb + (size_t)lrow * K + koff);
        cp16(sb2 + 16384 + lrow * 128 + sw16,      Bhb + (size_t)lrow * K + koff);
        cp16(sb2 + 16384 + lrow * 128 + 64 + sw16, Blb + (size_t)lrow * K + koff);
        cp_commit();
    };

    // prologue: 2 chunks in flight
    issue(0, 0);
    if (nchunks > 1) issue(1, 1);

    int buf = 0;
    for (int c = 0; c < nchunks; ++c) {
        // make sure chunk c has landed (keep at most the newest one pending)
        if (c + 1 < nchunks) cp_wait1(); else cp_wait0();
        __syncthreads();

        const uint32_t sa_u = smem_b + buf * STAGE;
        const uint32_t sb_u = sa_u + 16384;
#pragma unroll
        for (int ks = 0; ks < 2; ++ks) {
            uint32_t ah[2][4], al[2][4], bh[2][4], bl[2][4];
#pragma unroll
            for (int am = 0; am < 2; ++am) {
                int row = rowA_base + am * 16;
                uint32_t sw16 = (((2 * ks + khA) ^ (row & 3)) << 4);
                ldmx4(ah[am], sa_u + row * 128 + sw16);
                ldmx4(al[am], sa_u + row * 128 + 64 + sw16);
            }
#pragma unroll
            for (int pr = 0; pr < 2; ++pr) {
                int row = rowB_base + pr * 16;
                uint32_t sw16 = (((2 * ks + khB) ^ (row & 3)) << 4);
                ldmx4(bh[pr], sb_u + row * 128 + sw16);
                ldmx4(bl[pr], sb_u + row * 128 + 64 + sw16);
            }
#pragma unroll
            for (int am = 0; am < 2; ++am)
#pragma unroll
                for (int an = 0; an < 4; ++an)
                    mma16816(acc[am][an], ah[am], &bh[an >> 1][(an & 1) * 2]);
#pragma unroll
            for (int am = 0; am < 2; ++am)
#pragma unroll
                for (int an = 0; an < 4; ++an)
                    mma16816(acc[am][an], ah[am], &bl[an >> 1][(an & 1) * 2]);
#pragma unroll
            for (int am = 0; am < 2; ++am)
#pragma unroll
                for (int an = 0; an < 4; ++an)
                    mma16816(acc[am][an], al[am], &bh[an >> 1][(an & 1) * 2]);
        }
        __syncthreads();   // all warps done reading buf before it is refilled
        if (c + 2 < nchunks) issue(c + 2, (c + 2) % NSTAGE);
        buf = (buf + 1) % NSTAGE;
    }

    // ---- epilogue ----
#pragma unroll
    for (int am = 0; am < 2; ++am) {
        const int row0 = bm + warp_m * 32 + am * 16 + g;
#pragma unroll
        for (int an = 0; an < 4; ++an) {
            const int col = bn + warp_n * 32 + an * 8 + tig * 2;
            const float* d = acc[am][an];
            float2 o0 = make_float2(d[0], d[1]);
            float2 o1 = make_float2(d[2], d[3]);
            const size_t p0 = (size_t)row0 * N + col;
            const size_t p1 = (size_t)(row0 + 8) * N + col;
            if (EPI == 0) {
                *(float2*)(C + p0) = o0;
                *(float2*)(C + p1) = o1;
            } else if (EPI == 1) {
                float2 b2 = *(const float2*)(bias + col);
                float2 r0 = *(const float2*)(res + p0);
                float2 r1 = *(const float2*)(res + p1);
                o0.x += b2.x + r0.x; o0.y += b2.y + r0.y;
                o1.x += b2.x + r1.x; o1.y += b2.y + r1.y;
                *(float2*)(C + p0) = o0;
                *(float2*)(C + p1) = o1;
            } else if (EPI == 2) {
                float2 b2 = *(const float2*)(bias + col);
                o0.x += b2.x; o0.y += b2.y;
                o1.x += b2.x; o1.y += b2.y;
                *(float2*)(C + p0) = o0;
                *(float2*)(C + p1) = o1;
            } else {
                float2 b2 = *(const float2*)(bias + col);
                float2 g0 = *(const float2*)(res + p0);
                float2 g1 = *(const float2*)(res + p1);
                o0.x = siluf(g0.x) * (o0.x + b2.x);
                o0.y = siluf(g0.y) * (o0.y + b2.y);
                o1.x = siluf(g1.x) * (o1.x + b2.x);
                o1.y = siluf(g1.y) * (o1.y + b2.y);
                wr_hilo2(Oh, Ol, p0, o0.x, o0.y);
                wr_hilo2(Oh, Ol, p1, o1.x, o1.y);
            }
        }
    }
}

// ---------------------------------------------------------------------------
// fp32 -> bf16 hi/lo conversion (weights, pos_emb)
// ---------------------------------------------------------------------------
__global__ __launch_bounds__(256)
void cvt_kernel(const float* __restrict__ src, __nv_bfloat16* __restrict__ hi,
                __nv_bfloat16* __restrict__ lo, int n4)
{
    int i = blockIdx.x * blockDim.x + threadIdx.x;
    if (i >= n4) return;
    float4 v = ((const float4*)src)[i];
    wr_hilo4(hi, lo, (size_t)i * 4, v);
}

// ---------------------------------------------------------------------------
// RMSNorm -> bf16 hi/lo (optionally sigmoid-gated blend of x and x_token)
// ---------------------------------------------------------------------------
__global__ __launch_bounds__(256)
void rms_kernel(const float* __restrict__ X, const float* __restrict__ XT,
                const float* __restrict__ lcw, const float* __restrict__ W,
                __nv_bfloat16* __restrict__ Oh, __nv_bfloat16* __restrict__ Ol,
                int gated)
{
    const int row = blockIdx.x;
    const int tid = threadIdx.x;
    float4 xv = ((const float4*)(X + (size_t)row * 1024))[tid];
    if (gated) {
        float lc = 1.0f / (1.0f + expf(-lcw[0]));
        float om = 1.0f - lc;
        float4 tv = ((const float4*)(XT + (size_t)row * 1024))[tid];
        xv.x = lc * xv.x + om * tv.x;
        xv.y = lc * xv.y + om * tv.y;
        xv.z = lc * xv.z + om * tv.z;
        xv.w = lc * xv.w + om * tv.w;
    }
    float ss = xv.x * xv.x + xv.y * xv.y + xv.z * xv.z + xv.w * xv.w;
#pragma unroll
    for (int o = 16; o > 0; o >>= 1) ss += __shfl_xor_sync(0xffffffffu, ss, o);
    __shared__ float red[8];
    if ((tid & 31) == 0) red[tid >> 5] = ss;
    __syncthreads();
    float tot = red[0] + red[1] + red[2] + red[3] + red[4] + red[5] + red[6] + red[7];
    float rinv = rsqrtf(tot * (1.0f / 1024.0f) + 1e-5f);
    float4 wv = ((const float4*)W)[tid];
    float4 ov;
    ov.x = xv.x * rinv * wv.x;
    ov.y = xv.y * rinv * wv.y;
    ov.z = xv.z * rinv * wv.z;
    ov.w = xv.w * rinv * wv.w;
    wr_hilo4(Oh, Ol, (size_t)row * 1024 + tid * 4, ov);
}

// ---------------------------------------------------------------------------
// Causal attention, flash-style online softmax (fp32, f32x2 FMA).
// Single-key inner loop (R10 version, known good). Output -> bf16 hi/lo.
// ---------------------------------------------------------------------------
__global__ __launch_bounds__(128)
void attn_kernel(const float* __restrict__ Q, const float* __restrict__ Kg,
                 const float* __restrict__ V, __nv_bfloat16* __restrict__ Oh,
                 __nv_bfloat16* __restrict__ Ol)
{
    __shared__ float Ks[64][64];
    __shared__ float Vs[64][64];

    const int qt = blockIdx.x, h = blockIdx.y, b = blockIdx.z;
    const int q0 = qt * 128;
    const int tid = threadIdx.x;
    const int qidx = q0 + tid;

    unsigned long long q2[32], o2[32];
    {
        const float4* qp = (const float4*)(Q + (((size_t)(b * 2048 + qidx)) * 16 + h) * 64);
#pragma unroll
        for (int i = 0; i < 16; ++i) {
            float4 v = qp[i];
            q2[2 * i]     = pk2(v.x, v.y);
            q2[2 * i + 1] = pk2(v.z, v.w);
        }
    }
#pragma unroll
    for (int i = 0; i < 32; ++i) o2[i] = 0ULL;

    float mval = __int_as_float(0xff800000);  // -inf
    float l = 0.0f;
    const float scale = 0.03125f;

    for (int kt = 0; kt < q0 + 128; kt += 64) {
        __syncthreads();
#pragma unroll
        for (int i = 0; i < 8; ++i) {
            int u = tid + i * 128;
            int row = u >> 4, c4 = u & 15;
            ((float4*)&Ks[row][0])[c4] =
                *(const float4*)(Kg + (size_t)(kt + row) * 1024 + h * 64 + c4 * 4);
            ((float4*)&Vs[row][0])[c4] =
                *(const float4*)(V + (((size_t)(b * 2048 + kt + row)) * 16 + h) * 64 + c4 * 4);
        }
        __syncthreads();

        int jmax = qidx - kt + 1;
        if (jmax > 64) jmax = 64;
        for (int j = 0; j < jmax; ++j) {
            const unsigned long long* kp = (const unsigned long long*)&Ks[j][0];
            unsigned long long sa = 0ULL, sbb = 0ULL, sc = 0ULL, sd = 0ULL;
#pragma unroll
            for (int d = 0; d < 32; d += 4) {
                ffma2(sa,  q2[d],     kp[d]);
                ffma2(sbb, q2[d + 1], kp[d + 1]);
                ffma2(sc,  q2[d + 2], kp[d + 2]);
                ffma2(sd,  q2[d + 3], kp[d + 3]);
            }
            float2 pa = upk2(sa), pb = upk2(sbb), pc = upk2(sc), pd = upk2(sd);
            float s = ((pa.x + pa.y) + (pb.x + pb.y) + (pc.x + pc.y) + (pd.x + pd.y)) * scale;

            const unsigned long long* vp = (const unsigned long long*)&Vs[j][0];
            if (s <= mval) {
                float p = __expf(s - mval);
                l += p;
                unsigned long long pd2 = pk2(p, p);
#pragma unroll
                for (int d = 0; d < 32; ++d) ffma2(o2[d], pd2, vp[d]);
            } else {
                float f = __expf(mval - s);   // exp(-inf)=0 on first key
                mval = s;
                l = l * f + 1.0f;
                unsigned long long fd = pk2(f, f);
#pragma unroll
                for (int d = 0; d < 32; ++d) {
                    unsigned long long t = vp[d];    // t = o*f + v
                    ffma2(t, o2[d], fd);
                    o2[d] = t;
                }
            }
        }
    }

    float inv = 1.0f / l;
    unsigned long long iv = pk2(inv, inv);
    const size_t obase = ((size_t)(b * 2048 + qidx)) * 1024 + h * 64;
#pragma unroll
    for (int i = 0; i < 16; ++i) {
        float2 p0 = upk2(mul2(o2[2 * i], iv));
        float2 p1 = upk2(mul2(o2[2 * i + 1], iv));
        wr_hilo4(Oh, Ol, obase + i * 4, make_float4(p0.x, p0.y, p1.x, p1.y));
    }
}

// ---------------------------------------------------------------------------
// Launch
// ---------------------------------------------------------------------------
extern "C" void kernel_launch(void* const* d_in, const int* in_sizes, int n_in,
                              void* d_out, int out_size)
{
    const float* x       = (const float*)d_in[0];
    const float* x_token = (const float*)d_in[1];
    const float* pos_emb = (const float*)d_in[2];
    const float* lcw     = (const float*)d_in[3];
    const float* Wq      = (const float*)d_in[4];
    const float* Wk      = (const float*)d_in[5];
    const float* Wv      = (const float*)d_in[6];
    const float* proj_w  = (const float*)d_in[7];
    const float* proj_b  = (const float*)d_in[8];
    const float* w1_w    = (const float*)d_in[9];
    const float* w1_b    = (const float*)d_in[10];
    const float* w2_w    = (const float*)d_in[11];
    const float* w2_b    = (const float*)d_in[12];
    const float* w3_w    = (const float*)d_in[13];
    const float* w3_b    = (const float*)d_in[14];
    const float* n1w     = (const float*)d_in[15];
    const float* n2w     = (const float*)d_in[16];
    float* out = (float*)d_out;

    float *q, *k, *v, *xm, *h1;
    __nv_bfloat16* bf;
    cudaGetSymbolAddress((void**)&q,  g_q);
    cudaGetSymbolAddress((void**)&k,  g_k);
    cudaGetSymbolAddress((void**)&v,  g_v);
    cudaGetSymbolAddress((void**)&xm, g_xm);
    cudaGetSymbolAddress((void**)&h1, g_h1);
    cudaGetSymbolAddress((void**)&bf, g_bf);

    __nv_bfloat16 *wq_h = bf + O_WQ, *wq_l = wq_h + SZ_1M;
    __nv_bfloat16 *wk_h = bf + O_WK, *wk_l = wk_h + SZ_1M;
    __nv_bfloat16 *wv_h = bf + O_WV, *wv_l = wv_h + SZ_1M;
    __nv_bfloat16 *pw_h = bf + O_PW, *pw_l = pw_h + SZ_1M;
    __nv_bfloat16 *w1h  = bf + O_W1, *w1l  = w1h + SZ_4M;
    __nv_bfloat16 *w2h  = bf + O_W2, *w2l  = w2h + SZ_4M;
    __nv_bfloat16 *w3h  = bf + O_W3, *w3l  = w3h + SZ_4M;
    __nv_bfloat16 *pe_h = bf + O_PE, *pe_l = pe_h + SZ_2M;
    __nv_bfloat16 *xn_h = bf + O_XN, *xn_l = xn_h + SZ_4M;
    __nv_bfloat16 *at_h = bf + O_AT, *at_l = at_h + SZ_4M;
    __nv_bfloat16 *h_h  = bf + O_H,  *h_l  = h_h + SZ_16M;

    cudaFuncSetAttribute(mma_gemm<0>, cudaFuncAttributeMaxDynamicSharedMemorySize, MM_SMEM);
    cudaFuncSetAttribute(mma_gemm<1>, cudaFuncAttributeMaxDynamicSharedMemorySize, MM_SMEM);
    cudaFuncSetAttribute(mma_gemm<2>, cudaFuncAttributeMaxDynamicSharedMemorySize, MM_SMEM);
    cudaFuncSetAttribute(mma_gemm<3>, cudaFuncAttributeMaxDynamicSharedMemorySize, MM_SMEM);

    // 0) convert weights + pos_emb to bf16 hi/lo
    cvt_kernel<<<SZ_1M / 4 / 256, 256>>>(Wq,      wq_h, wq_l, SZ_1M / 4);
    cvt_kernel<<<SZ_1M / 4 / 256, 256>>>(Wk,      wk_h, wk_l, SZ_1M / 4);
    cvt_kernel<<<SZ_1M / 4 / 256, 256>>>(Wv,      wv_h, wv_l, SZ_1M / 4);
    cvt_kernel<<<SZ_1M / 4 / 256, 256>>>(proj_w,  pw_h, pw_l, SZ_1M / 4);
    cvt_kernel<<<SZ_4M / 4 / 256, 256>>>(w1_w,    w1h,  w1l,  SZ_4M / 4);
    cvt_kernel<<<SZ_4M / 4 / 256, 256>>>(w2_w,    w2h,  w2l,  SZ_4M / 4);
    cvt_kernel<<<SZ_4M / 4 / 256, 256>>>(w3_w,    w3h,  w3l,  SZ_4M / 4);
    cvt_kernel<<<SZ_2M / 4 / 256, 256>>>(pos_emb, pe_h, pe_l, SZ_2M / 4);

    // 1) gated rmsnorm -> xn (bf16 hi/lo)
    rms_kernel<<<4096, 256>>>(x, x_token, lcw, n1w, xn_h, xn_l, 1);
    // 2) q = xn @ Wq^T ; k = pos_emb @ Wk^T ; v = xn @ Wv^T  (fp32 outs)
    mma_gemm<0><<<dim3(8, 32), 512, MM_SMEM>>>(xn_h, xn_l, wq_h, wq_l, nullptr, nullptr, q, nullptr, nullptr, 4096, 1024, 1024);
    mma_gemm<0><<<dim3(8, 16), 512, MM_SMEM>>>(pe_h, pe_l, wk_h, wk_l, nullptr, nullptr, k, nullptr, nullptr, 2048, 1024, 1024);
    mma_gemm<0><<<dim3(8, 32), 512, MM_SMEM>>>(xn_h, xn_l, wv_h, wv_l, nullptr, nullptr, v, nullptr, nullptr, 4096, 1024, 1024);
    // 3) causal attention -> at (bf16 hi/lo)
    attn_kernel<<<dim3(16, 16, 2), 128>>>(q, k, v, at_h, at_l);
    // 4) x_mid = x + attn @ proj_w^T + proj_b  (fp32)
    mma_gemm<1><<<dim3(8, 32), 512, MM_SMEM>>>(at_h, at_l, pw_h, pw_l, proj_b, x, xm, nullptr, nullptr, 4096, 1024, 1024);
    // 5) xn2 = rmsnorm(x_mid) -> xn (bf16 hi/lo)
    rms_kernel<<<4096, 256>>>(xm, nullptr, nullptr, n2w, xn_h, xn_l, 0);
    // 6) h1 = xn2 @ w1^T + b1 (fp32) ; h = silu(h1)*(xn2 @ w3^T + b3) -> bf16
    mma_gemm<2><<<dim3(32, 32), 512, MM_SMEM>>>(xn_h, xn_l, w1h, w1l, w1_b, nullptr, h1, nullptr, nullptr, 4096, 4096, 1024);
    mma_gemm<3><<<dim3(32, 32), 512, MM_SMEM>>>(xn_h, xn_l, w3h, w3l, w3_b, h1, nullptr, h_h, h_l, 4096, 4096, 1024);
    // 7) out = x_mid + h @ w2^T + b2  (fp32)
    mma_gemm<1><<<dim3(8, 32), 512, MM_SMEM>>>(h_h, h_l, w2h, w2l, w2_b, xm, out, nullptr, nullptr, 4096, 1024, 4096);
}

// round 15
// speedup vs baseline: 1.6208x; 1.6208x over previous
#include <cuda_runtime.h>
#include <cuda_bf16.h>
#include <cstdint>
#include <cstddef>

// ---------------------------------------------------------------------------
// Scratch (static __device__ arrays; no allocation anywhere)
// ---------------------------------------------------------------------------
__device__ float g_xm[4096 * 1024];     // x + attn proj (residual mid)
__device__ float g_h1[4096 * 4096];     // FFN pre-gate (w1 out), fp32

// bf16 hi/lo pool: for each tensor, [hi | lo] contiguous
#define SZ_1M  1048576
#define SZ_2M  2097152
#define SZ_4M  4194304
#define SZ_16M 16777216
#define O_WQ 0
#define O_WK (O_WQ + 2 * SZ_1M)
#define O_WV (O_WK + 2 * SZ_1M)
#define O_PW (O_WV + 2 * SZ_1M)
#define O_W1 (O_PW + 2 * SZ_1M)
#define O_W2 (O_W1 + 2 * SZ_4M)
#define O_W3 (O_W2 + 2 * SZ_4M)
#define O_PE (O_W3 + 2 * SZ_4M)
#define O_XN (O_PE + 2 * SZ_2M)
#define O_AT (O_XN + 2 * SZ_4M)
#define O_H  (O_AT + 2 * SZ_4M)
#define O_QB (O_H  + 2 * SZ_16M)
#define O_KB (O_QB + 2 * SZ_4M)
#define O_VB (O_KB + 2 * SZ_2M)
#define BF_TOTAL (O_VB + 2 * SZ_4M)
__device__ __nv_bfloat16 g_bf[BF_TOTAL];

// ---------------------------------------------------------------------------
// helpers
// ---------------------------------------------------------------------------
__device__ __forceinline__ float siluf(float z) { return z / (1.0f + expf(-z)); }

// write 2 consecutive values as bf16 hi/lo
__device__ __forceinline__ void wr_hilo2(__nv_bfloat16* H, __nv_bfloat16* L,
                                         size_t p, float a, float b) {
    __nv_bfloat16 ha = __float2bfloat16(a), hb = __float2bfloat16(b);
    __nv_bfloat16 la = __float2bfloat16(a - __bfloat162float(ha));
    __nv_bfloat16 lb = __float2bfloat16(b - __bfloat162float(hb));
    *(uint32_t*)(H + p) = (uint32_t)__bfloat16_as_ushort(ha) |
                          ((uint32_t)__bfloat16_as_ushort(hb) << 16);
    *(uint32_t*)(L + p) = (uint32_t)__bfloat16_as_ushort(la) |
                          ((uint32_t)__bfloat16_as_ushort(lb) << 16);
}
// write 4 consecutive values as bf16 hi/lo (8B stores)
__device__ __forceinline__ void wr_hilo4(__nv_bfloat16* H, __nv_bfloat16* L,
                                         size_t p, float4 v) {
    __nv_bfloat16 h0 = __float2bfloat16(v.x), h1 = __float2bfloat16(v.y),
                  h2 = __float2bfloat16(v.z), h3 = __float2bfloat16(v.w);
    __nv_bfloat16 l0 = __float2bfloat16(v.x - __bfloat162float(h0));
    __nv_bfloat16 l1 = __float2bfloat16(v.y - __bfloat162float(h1));
    __nv_bfloat16 l2 = __float2bfloat16(v.z - __bfloat162float(h2));
    __nv_bfloat16 l3 = __float2bfloat16(v.w - __bfloat162float(h3));
    uint2 hp, lp;
    hp.x = (uint32_t)__bfloat16_as_ushort(h0) | ((uint32_t)__bfloat16_as_ushort(h1) << 16);
    hp.y = (uint32_t)__bfloat16_as_ushort(h2) | ((uint32_t)__bfloat16_as_ushort(h3) << 16);
    lp.x = (uint32_t)__bfloat16_as_ushort(l0) | ((uint32_t)__bfloat16_as_ushort(l1) << 16);
    lp.y = (uint32_t)__bfloat16_as_ushort(l2) | ((uint32_t)__bfloat16_as_ushort(l3) << 16);
    *(uint2*)(H + p) = hp;
    *(uint2*)(L + p) = lp;
}

__device__ __forceinline__ uint32_t smem_u32(const void* p) {
    uint32_t a;
    asm("{ .reg .u64 t; cvta.to.shared.u64 t, %1; cvt.u32.u64 %0, t; }"
        : "=r"(a) : "l"(p));
    return a;
}
__device__ __forceinline__ void ldmx4(uint32_t* r, uint32_t addr) {
    asm volatile("ldmatrix.sync.aligned.m8n8.x4.shared.b16 {%0,%1,%2,%3}, [%4];"
                 : "=r"(r[0]), "=r"(r[1]), "=r"(r[2]), "=r"(r[3]) : "r"(addr));
}
__device__ __forceinline__ void ldmx4t(uint32_t* r, uint32_t addr) {
    asm volatile("ldmatrix.sync.aligned.m8n8.x4.trans.shared.b16 {%0,%1,%2,%3}, [%4];"
                 : "=r"(r[0]), "=r"(r[1]), "=r"(r[2]), "=r"(r[3]) : "r"(addr));
}
__device__ __forceinline__ void mma16816(float* d, const uint32_t* a,
                                         const uint32_t* b) {
    asm volatile(
        "mma.sync.aligned.m16n8k16.row.col.f32.bf16.bf16.f32 "
        "{%0,%1,%2,%3}, {%4,%5,%6,%7}, {%8,%9}, {%0,%1,%2,%3};"
        : "+f"(d[0]), "+f"(d[1]), "+f"(d[2]), "+f"(d[3])
        : "r"(a[0]), "r"(a[1]), "r"(a[2]), "r"(a[3]), "r"(b[0]), "r"(b[1]));
}
__device__ __forceinline__ void cp16(uint32_t dst, const void* src) {
    asm volatile("cp.async.cg.shared.global [%0], [%1], 16;"
                 :: "r"(dst), "l"(src) : "memory");
}
__device__ __forceinline__ void cp_commit() {
    asm volatile("cp.async.commit_group;" ::: "memory");
}
__device__ __forceinline__ void cp_wait0() {
    asm volatile("cp.async.wait_group 0;" ::: "memory");
}
__device__ __forceinline__ void cp_wait1() {
    asm volatile("cp.async.wait_group 1;" ::: "memory");
}

// ---------------------------------------------------------------------------
// Tensor-core GEMM (R13 config): C[M,N] = A[M,K]*B[N,K]^T, bf16 hi/lo in GMEM.
// 3-term: Ah*Bh + Ah*Bl + Al*Bh. 128x128x64 tile, 512 threads, 3-stage cp.async.
// smem row = 256B [hi 128B | lo 128B], 16B chunks xor-swizzled by (row&7).
// EPI: 0 fp32 | 1 res+acc+bias fp32 | 2 acc+bias fp32
//      3 silu(res)*(acc+bias)->bf16 hi/lo | 4 acc*sc -> bf16 hi/lo
// ---------------------------------------------------------------------------
#define MBM 128
#define MBN 128
#define MBK 64
#define STAGE 65536
#define NSTAGE 3
#define MM_SMEM (NSTAGE * STAGE)

template <int EPI>
__global__ __launch_bounds__(512)
void mma_gemm(const __nv_bfloat16* __restrict__ Ah, const __nv_bfloat16* __restrict__ Al,
              const __nv_bfloat16* __restrict__ Bh, const __nv_bfloat16* __restrict__ Bl,
              const float* __restrict__ bias, const float* __restrict__ res,
              float* __restrict__ C, __nv_bfloat16* __restrict__ Oh,
              __nv_bfloat16* __restrict__ Ol, int M, int N, int K, float sc)
{
    extern __shared__ char smem[];
    const uint32_t smem_b = smem_u32(smem);
    const int tid = threadIdx.x;
    const int wid = tid >> 5;
    const int lid = tid & 31;
    const int warp_m = wid >> 2;
    const int warp_n = wid & 3;
    const int bm = blockIdx.y * MBM;
    const int bn = blockIdx.x * MBN;

    const int g   = lid >> 2;
    const int tig = lid & 3;
    const int mat = lid >> 3;
    const int rwi = lid & 7;

    const int rowA_base = warp_m * 32 + rwi + (mat & 1) * 8;
    const int khA       = mat >> 1;
    const int rowB_base = warp_n * 32 + (mat >> 1) * 8 + rwi;
    const int khB       = mat & 1;

    float acc[2][4][4];
#pragma unroll
    for (int i = 0; i < 2; ++i)
#pragma unroll
        for (int j = 0; j < 4; ++j)
#pragma unroll
            for (int q = 0; q < 4; ++q) acc[i][j][q] = 0.0f;

    const __nv_bfloat16* Ahb = Ah + (size_t)bm * K;
    const __nv_bfloat16* Alb = Al + (size_t)bm * K;
    const __nv_bfloat16* Bhb = Bh + (size_t)bn * K;
    const __nv_bfloat16* Blb = Bl + (size_t)bn * K;
    const int nchunks = K / MBK;

    const int lrow_lo = tid >> 3;
    const int lch     = tid & 7;

    auto issue = [&](int kc, int stage) {
        const uint32_t sb2 = smem_b + stage * STAGE;
        const size_t koff = (size_t)kc * MBK + lch * 8;
#pragma unroll
        for (int i = 0; i < 8; ++i) {
            const int comp = i >> 1;
            const int row  = lrow_lo + (i & 1) * 64;
            const uint32_t sw16 = (uint32_t)(((lch ^ (row & 7)) << 4));
            uint32_t dst;
            const __nv_bfloat16* src;
            if (comp == 0)      { dst = sb2 + row * 256 + sw16;               src = Ahb + (size_t)row * K + koff; }
            else if (comp == 1) { dst = sb2 + row * 256 + 128 + sw16;         src = Alb + (size_t)row * K + koff; }
            else if (comp == 2) { dst = sb2 + 32768 + row * 256 + sw16;       src = Bhb + (size_t)row * K + koff; }
            else                { dst = sb2 + 32768 + row * 256 + 128 + sw16; src = Blb + (size_t)row * K + koff; }
            cp16(dst, src);
        }
        cp_commit();
    };

    issue(0, 0);
    if (nchunks > 1) issue(1, 1);

    int buf = 0;
    for (int c = 0; c < nchunks; ++c) {
        if (c + 1 < nchunks) cp_wait1(); else cp_wait0();
        __syncthreads();

        const uint32_t sa_u = smem_b + buf * STAGE;
        const uint32_t sb_u = sa_u + 32768;
#pragma unroll
        for (int ks = 0; ks < 4; ++ks) {
            uint32_t ah[2][4], al[2][4], bh[2][4], bl[2][4];
#pragma unroll
            for (int am = 0; am < 2; ++am) {
                int row = rowA_base + am * 16;
                uint32_t sw16 = (((2 * ks + khA) ^ (row & 7)) << 4);
                ldmx4(ah[am], sa_u + row * 256 + sw16);
                ldmx4(al[am], sa_u + row * 256 + 128 + sw16);
            }
#pragma unroll
            for (int pr = 0; pr < 2; ++pr) {
                int row = rowB_base + pr * 16;
                uint32_t sw16 = (((2 * ks + khB) ^ (row & 7)) << 4);
                ldmx4(bh[pr], sb_u + row * 256 + sw16);
                ldmx4(bl[pr], sb_u + row * 256 + 128 + sw16);
            }
#pragma unroll
            for (int am = 0; am < 2; ++am)
#pragma unroll
                for (int an = 0; an < 4; ++an)
                    mma16816(acc[am][an], ah[am], &bh[an >> 1][(an & 1) * 2]);
#pragma unroll
            for (int am = 0; am < 2; ++am)
#pragma unroll
                for (int an = 0; an < 4; ++an)
                    mma16816(acc[am][an], ah[am], &bl[an >> 1][(an & 1) * 2]);
#pragma unroll
            for (int am = 0; am < 2; ++am)
#pragma unroll
                for (int an = 0; an < 4; ++an)
                    mma16816(acc[am][an], al[am], &bh[an >> 1][(an & 1) * 2]);
        }
        __syncthreads();
        if (c + 2 < nchunks) issue(c + 2, (c + 2) % NSTAGE);
        buf = (buf + 1) % NSTAGE;
    }

#pragma unroll
    for (int am = 0; am < 2; ++am) {
        const int row0 = bm + warp_m * 32 + am * 16 + g;
#pragma unroll
        for (int an = 0; an < 4; ++an) {
            const int col = bn + warp_n * 32 + an * 8 + tig * 2;
            const float* d = acc[am][an];
            float2 o0 = make_float2(d[0], d[1]);
            float2 o1 = make_float2(d[2], d[3]);
            const size_t p0 = (size_t)row0 * N + col;
            const size_t p1 = (size_t)(row0 + 8) * N + col;
            if (EPI == 0) {
                *(float2*)(C + p0) = o0;
                *(float2*)(C + p1) = o1;
            } else if (EPI == 1) {
                float2 b2 = *(const float2*)(bias + col);
                float2 r0 = *(const float2*)(res + p0);
                float2 r1 = *(const float2*)(res + p1);
                o0.x += b2.x + r0.x; o0.y += b2.y + r0.y;
                o1.x += b2.x + r1.x; o1.y += b2.y + r1.y;
                *(float2*)(C + p0) = o0;
                *(float2*)(C + p1) = o1;
            } else if (EPI == 2) {
                float2 b2 = *(const float2*)(bias + col);
                o0.x += b2.x; o0.y += b2.y;
                o1.x += b2.x; o1.y += b2.y;
                *(float2*)(C + p0) = o0;
                *(float2*)(C + p1) = o1;
            } else if (EPI == 3) {
                float2 b2 = *(const float2*)(bias + col);
                float2 g0 = *(const float2*)(res + p0);
                float2 g1 = *(const float2*)(res + p1);
                o0.x = siluf(g0.x) * (o0.x + b2.x);
                o0.y = siluf(g0.y) * (o0.y + b2.y);
                o1.x = siluf(g1.x) * (o1.x + b2.x);
                o1.y = siluf(g1.y) * (o1.y + b2.y);
                wr_hilo2(Oh, Ol, p0, o0.x, o0.y);
                wr_hilo2(Oh, Ol, p1, o1.x, o1.y);
            } else {
                o0.x *= sc; o0.y *= sc; o1.x *= sc; o1.y *= sc;
                wr_hilo2(Oh, Ol, p0, o0.x, o0.y);
                wr_hilo2(Oh, Ol, p1, o1.x, o1.y);
            }
        }
    }
}

// ---------------------------------------------------------------------------
// fp32 -> bf16 hi/lo conversion (weights, pos_emb)
// ---------------------------------------------------------------------------
__global__ __launch_bounds__(256)
void cvt_kernel(const float* __restrict__ src, __nv_bfloat16* __restrict__ hi,
                __nv_bfloat16* __restrict__ lo, int n4)
{
    int i = blockIdx.x * blockDim.x + threadIdx.x;
    if (i >= n4) return;
    float4 v = ((const float4*)src)[i];
    wr_hilo4(hi, lo, (size_t)i * 4, v);
}

// ---------------------------------------------------------------------------
// RMSNorm -> bf16 hi/lo (optionally sigmoid-gated blend of x and x_token)
// ---------------------------------------------------------------------------
__global__ __launch_bounds__(256)
void rms_kernel(const float* __restrict__ X, const float* __restrict__ XT,
                const float* __restrict__ lcw, const float* __restrict__ W,
                __nv_bfloat16* __restrict__ Oh, __nv_bfloat16* __restrict__ Ol,
                int gated)
{
    const int row = blockIdx.x;
    const int tid = threadIdx.x;
    float4 xv = ((const float4*)(X + (size_t)row * 1024))[tid];
    if (gated) {
        float lc = 1.0f / (1.0f + expf(-lcw[0]));
        float om = 1.0f - lc;
        float4 tv = ((const float4*)(XT + (size_t)row * 1024))[tid];
        xv.x = lc * xv.x + om * tv.x;
        xv.y = lc * xv.y + om * tv.y;
        xv.z = lc * xv.z + om * tv.z;
        xv.w = lc * xv.w + om * tv.w;
    }
    float ss = xv.x * xv.x + xv.y * xv.y + xv.z * xv.z + xv.w * xv.w;
#pragma unroll
    for (int o = 16; o > 0; o >>= 1) ss += __shfl_xor_sync(0xffffffffu, ss, o);
    __shared__ float red[8];
    if ((tid & 31) == 0) red[tid >> 5] = ss;
    __syncthreads();
    float tot = red[0] + red[1] + red[2] + red[3] + red[4] + red[5] + red[6] + red[7];
    float rinv = rsqrtf(tot * (1.0f / 1024.0f) + 1e-5f);
    float4 wv = ((const float4*)W)[tid];
    float4 ov;
    ov.x = xv.x * rinv * wv.x;
    ov.y = xv.y * rinv * wv.y;
    ov.z = xv.z * rinv * wv.z;
    ov.w = xv.w * rinv * wv.w;
    wr_hilo4(Oh, Ol, (size_t)row * 1024 + tid * 4, ov);
}

// ---------------------------------------------------------------------------
// Tensor-core causal flash attention.
// Block = (128 q rows, head h, batch b), 128 threads = 4 warps.
// Warp w owns q rows [w*32, w*32+32), full 64-d head, all key tiles (64 keys).
// Q pre-scaled by D^-0.5 in the q GEMM. 3-term hi/lo for both QK^T and PV.
// smem: Q 32K | K 16K | V 16K | P 32K = 96KB -> 2 blocks/SM.
// ---------------------------------------------------------------------------
#define AT_SMEM 98304

__global__ __launch_bounds__(128, 2)
void attn_mma(const __nv_bfloat16* __restrict__ Qh, const __nv_bfloat16* __restrict__ Ql,
              const __nv_bfloat16* __restrict__ Kh, const __nv_bfloat16* __restrict__ Kl,
              const __nv_bfloat16* __restrict__ Vh, const __nv_bfloat16* __restrict__ Vl,
              __nv_bfloat16* __restrict__ Oh, __nv_bfloat16* __restrict__ Ol)
{
    extern __shared__ char smem[];
    const uint32_t sb = smem_u32(smem);
    const int qt = blockIdx.x, h = blockIdx.y, b = blockIdx.z;
    const int q0 = qt * 128;
    const int tid = threadIdx.x;
    const int wid = tid >> 5;
    const int lid = tid & 31;
    const int g = lid >> 2, tig = lid & 3;
    const int mat = lid >> 3, rwi = lid & 7;
    const uint32_t AQ = sb, AK = sb + 32768, AV = sb + 49152, AP = sb + 65536;
    const float NEGINF = __int_as_float(0xff800000);

    // load Q tile (128 rows x 64d hi/lo): one row per thread
    {
        const int row = tid;
        const size_t gq = ((size_t)(b * 2048 + q0 + row)) * 1024 + h * 64;
#pragma unroll
        for (int cc = 0; cc < 8; ++cc) {
            const uint32_t sw = (uint32_t)(((cc ^ (row & 7)) << 4));
            cp16(AQ + row * 256 + sw,       Qh + gq + cc * 8);
            cp16(AQ + row * 256 + 128 + sw, Ql + gq + cc * 8);
        }
        cp_commit();
    }

    float oacc[2][8][4];
#pragma unroll
    for (int i = 0; i < 2; ++i)
#pragma unroll
        for (int j = 0; j < 8; ++j)
#pragma unroll
            for (int q = 0; q < 4; ++q) oacc[i][j][q] = 0.0f;
    float mrow[4], lrow[4];
#pragma unroll
    for (int i = 0; i < 4; ++i) { mrow[i] = NEGINF; lrow[i] = 0.0f; }

    const int ntiles = qt * 2 + 2;
    for (int t = 0; t < ntiles; ++t) {
        const int kt = t * 64;
        // load K/V tile: thread -> (row = tid>>1, K or V by tid&1)
        {
            const int row = tid >> 1;
            const int isv = tid & 1;
            const size_t gk = (size_t)(kt + row) * 1024 + h * 64;
            const size_t gv = ((size_t)(b * 2048 + kt + row)) * 1024 + h * 64;
            const __nv_bfloat16* sh = isv ? (Vh + gv) : (Kh + gk);
            const __nv_bfloat16* sl = isv ? (Vl + gv) : (Kl + gk);
            const uint32_t dstb = (isv ? AV : AK) + row * 256;
#pragma unroll
            for (int cc = 0; cc < 8; ++cc) {
                const uint32_t sw = (uint32_t)(((cc ^ (row & 7)) << 4));
                cp16(dstb + sw,       sh + cc * 8);
                cp16(dstb + 128 + sw, sl + cc * 8);
            }
            cp_commit();
        }
        cp_wait0();
        __syncthreads();

        // ---- S = Q K^T (3-term) ----
        float sacc[2][8][4];
#pragma unroll
        for (int i = 0; i < 2; ++i)
#pragma unroll
            for (int j = 0; j < 8; ++j)
#pragma unroll
                for (int q = 0; q < 4; ++q) sacc[i][j][q] = 0.0f;
#pragma unroll
        for (int ks = 0; ks < 4; ++ks) {
            uint32_t qh2[2][4], ql2[2][4], kh2[4][4], kl2[4][4];
#pragma unroll
            for (int am = 0; am < 2; ++am) {
                const int row = wid * 32 + am * 16 + rwi + (mat & 1) * 8;
                const uint32_t sw = (uint32_t)((((2 * ks + (mat >> 1)) ^ (row & 7)) << 4));
                ldmx4(qh2[am], AQ + row * 256 + sw);
                ldmx4(ql2[am], AQ + row * 256 + 128 + sw);
            }
#pragma unroll
            for (int pr = 0; pr < 4; ++pr) {
                const int row = pr * 16 + (mat >> 1) * 8 + rwi;
                const uint32_t sw = (uint32_t)((((2 * ks + (mat & 1)) ^ (row & 7)) << 4));
                ldmx4(kh2[pr], AK + row * 256 + sw);
                ldmx4(kl2[pr], AK + row * 256 + 128 + sw);
            }
#pragma unroll
            for (int am = 0; am < 2; ++am)
#pragma unroll
                for (int an = 0; an < 8; ++an)
                    mma16816(sacc[am][an], qh2[am], &kh2[an >> 1][(an & 1) * 2]);
#pragma unroll
            for (int am = 0; am < 2; ++am)
#pragma unroll
                for (int an = 0; an < 8; ++an)
                    mma16816(sacc[am][an], qh2[am], &kl2[an >> 1][(an & 1) * 2]);
#pragma unroll
            for (int am = 0; am < 2; ++am)
#pragma unroll
                for (int an = 0; an < 8; ++an)
                    mma16816(sacc[am][an], ql2[am], &kh2[an >> 1][(an & 1) * 2]);
        }

        // ---- online softmax per row-slot ----
        const bool need_mask = (kt + 63 > q0 + wid * 32);
#pragma unroll
        for (int rs = 0; rs < 4; ++rs) {
            const int am = rs >> 1, hh = rs & 1;
            const int prow = wid * 32 + am * 16 + g + 8 * hh;
            const int row_g = q0 + prow;
            float v16[16];
#pragma unroll
            for (int an = 0; an < 8; ++an) {
                v16[an * 2]     = sacc[am][an][hh * 2];
                v16[an * 2 + 1] = sacc[am][an][hh * 2 + 1];
            }
            if (need_mask) {
#pragma unroll
                for (int an = 0; an < 8; ++an) {
                    const int c0 = kt + an * 8 + tig * 2;
                    if (c0 > row_g)     v16[an * 2]     = NEGINF;
                    if (c0 + 1 > row_g) v16[an * 2 + 1] = NEGINF;
                }
            }
            float rmax = v16[0];
#pragma unroll
            for (int i = 1; i < 16; ++i) rmax = fmaxf(rmax, v16[i]);
            rmax = fmaxf(rmax, __shfl_xor_sync(0xffffffffu, rmax, 1));
            rmax = fmaxf(rmax, __shfl_xor_sync(0xffffffffu, rmax, 2));
            const float mn = fmaxf(mrow[rs], rmax);
            const float f = __expf(mrow[rs] - mn);
            mrow[rs] = mn;
            float sum = 0.0f;
#pragma unroll
            for (int i = 0; i < 16; ++i) { v16[i] = __expf(v16[i] - mn); sum += v16[i]; }
            sum += __shfl_xor_sync(0xffffffffu, sum, 1);
            sum += __shfl_xor_sync(0xffffffffu, sum, 2);
            lrow[rs] = lrow[rs] * f + sum;
#pragma unroll
            for (int an = 0; an < 8; ++an) {
                oacc[am][an][hh * 2]     *= f;
                oacc[am][an][hh * 2 + 1] *= f;
            }
            // write P (bf16 hi/lo) to smem, swizzled
            const uint32_t pb = AP + prow * 256 + tig * 4;
#pragma unroll
            for (int an = 0; an < 8; ++an) {
                const uint32_t sw = (uint32_t)(((an ^ (prow & 7)) << 4));
                float a = v16[an * 2], b2 = v16[an * 2 + 1];
                __nv_bfloat16 ha = __float2bfloat16(a), hb = __float2bfloat16(b2);
                __nv_bfloat16 la = __float2bfloat16(a - __bfloat162float(ha));
                __nv_bfloat16 lb = __float2bfloat16(b2 - __bfloat162float(hb));
                uint32_t hw = (uint32_t)__bfloat16_as_ushort(ha) |
                              ((uint32_t)__bfloat16_as_ushort(hb) << 16);
                uint32_t lw = (uint32_t)__bfloat16_as_ushort(la) |
                              ((uint32_t)__bfloat16_as_ushort(lb) << 16);
                asm volatile("st.shared.b32 [%0], %1;" :: "r"(pb + sw), "r"(hw));
                asm volatile("st.shared.b32 [%0], %1;" :: "r"(pb + 128 + sw), "r"(lw));
            }
        }
        __syncwarp();

        // ---- O += P V (3-term, V via trans-ldmatrix) ----
#pragma unroll
        for (int ks = 0; ks < 4; ++ks) {
            uint32_t ph2[2][4], pl2[2][4], vh2[4][4], vl2[4][4];
#pragma unroll
            for (int am = 0; am < 2; ++am) {
                const int row = wid * 32 + am * 16 + rwi + (mat & 1) * 8;
                const uint32_t sw = (uint32_t)((((2 * ks + (mat >> 1)) ^ (row & 7)) << 4));
                ldmx4(ph2[am], AP + row * 256 + sw);
                ldmx4(pl2[am], AP + row * 256 + 128 + sw);
            }
#pragma unroll
            for (int pr = 0; pr < 4; ++pr) {
                const int row = ks * 16 + (mat & 1) * 8 + rwi;
                const uint32_t sw = (uint32_t)((((pr * 2 + (mat >> 1)) ^ (row & 7)) << 4));
                ldmx4t(vh2[pr], AV + row * 256 + sw);
                ldmx4t(vl2[pr], AV + row * 256 + 128 + sw);
            }
#pragma unroll
            for (int am = 0; am < 2; ++am)
#pragma unroll
                for (int an = 0; an < 8; ++an)
                    mma16816(oacc[am][an], ph2[am], &vh2[an >> 1][(an & 1) * 2]);
#pragma unroll
            for (int am = 0; am < 2; ++am)
#pragma unroll
                for (int an = 0; an < 8; ++an)
                    mma16816(oacc[am][an], ph2[am], &vl2[an >> 1][(an & 1) * 2]);
#pragma unroll
            for (int am = 0; am < 2; ++am)
#pragma unroll
                for (int an = 0; an < 8; ++an)
                    mma16816(oacc[am][an], pl2[am], &vh2[an >> 1][(an & 1) * 2]);
        }
        __syncthreads();   // all warps done with K/V before next tile's load
    }

    // ---- epilogue: O /= l, write bf16 hi/lo ----
#pragma unroll
    for (int rs = 0; rs < 4; ++rs) {
        const int am = rs >> 1, hh = rs & 1;
        const int prow = wid * 32 + am * 16 + g + 8 * hh;
        const float inv = 1.0f / lrow[rs];
        const size_t gb = ((size_t)(b * 2048 + q0 + prow)) * 1024 + h * 64;
#pragma unroll
        for (int an = 0; an < 8; ++an) {
            const int col = an * 8 + tig * 2;
            wr_hilo2(Oh, Ol, gb + col,
                     oacc[am][an][hh * 2] * inv, oacc[am][an][hh * 2 + 1] * inv);
        }
    }
}

// ---------------------------------------------------------------------------
// Launch
// ---------------------------------------------------------------------------
extern "C" void kernel_launch(void* const* d_in, const int* in_sizes, int n_in,
                              void* d_out, int out_size)
{
    const float* x       = (const float*)d_in[0];
    const float* x_token = (const float*)d_in[1];
    const float* pos_emb = (const float*)d_in[2];
    const float* lcw     = (const float*)d_in[3];
    const float* Wq      = (const float*)d_in[4];
    const float* Wk      = (const float*)d_in[5];
    const float* Wv      = (const float*)d_in[6];
    const float* proj_w  = (const float*)d_in[7];
    const float* proj_b  = (const float*)d_in[8];
    const float* w1_w    = (const float*)d_in[9];
    const float* w1_b    = (const float*)d_in[10];
    const float* w2_w    = (const float*)d_in[11];
    const float* w2_b    = (const float*)d_in[12];
    const float* w3_w    = (const float*)d_in[13];
    const float* w3_b    = (const float*)d_in[14];
    const float* n1w     = (const float*)d_in[15];
    const float* n2w     = (const float*)d_in[16];
    float* out = (float*)d_out;

    float *xm, *h1;
    __nv_bfloat16* bf;
    cudaGetSymbolAddress((void**)&xm, g_xm);
    cudaGetSymbolAddress((void**)&h1, g_h1);
    cudaGetSymbolAddress((void**)&bf, g_bf);

    __nv_bfloat16 *wq_h = bf + O_WQ, *wq_l = wq_h + SZ_1M;
    __nv_bfloat16 *wk_h = bf + O_WK, *wk_l = wk_h + SZ_1M;
    __nv_bfloat16 *wv_h = bf + O_WV, *wv_l = wv_h + SZ_1M;
    __nv_bfloat16 *pw_h = bf + O_PW, *pw_l = pw_h + SZ_1M;
    __nv_bfloat16 *w1h  = bf + O_W1, *w1l  = w1h + SZ_4M;
    __nv_bfloat16 *w2h  = bf + O_W2, *w2l  = w2h + SZ_4M;
    __nv_bfloat16 *w3h  = bf + O_W3, *w3l  = w3h + SZ_4M;
    __nv_bfloat16 *pe_h = bf + O_PE, *pe_l = pe_h + SZ_2M;
    __nv_bfloat16 *xn_h = bf + O_XN, *xn_l = xn_h + SZ_4M;
    __nv_bfloat16 *at_h = bf + O_AT, *at_l = at_h + SZ_4M;
    __nv_bfloat16 *h_h  = bf + O_H,  *h_l  = h_h + SZ_16M;
    __nv_bfloat16 *q_h  = bf + O_QB, *q_l  = q_h + SZ_4M;
    __nv_bfloat16 *k_h  = bf + O_KB, *k_l  = k_h + SZ_2M;
    __nv_bfloat16 *v_h  = bf + O_VB, *v_l  = v_h + SZ_4M;

    cudaFuncSetAttribute(mma_gemm<0>, cudaFuncAttributeMaxDynamicSharedMemorySize, MM_SMEM);
    cudaFuncSetAttribute(mma_gemm<1>, cudaFuncAttributeMaxDynamicSharedMemorySize, MM_SMEM);
    cudaFuncSetAttribute(mma_gemm<2>, cudaFuncAttributeMaxDynamicSharedMemorySize, MM_SMEM);
    cudaFuncSetAttribute(mma_gemm<3>, cudaFuncAttributeMaxDynamicSharedMemorySize, MM_SMEM);
    cudaFuncSetAttribute(mma_gemm<4>, cudaFuncAttributeMaxDynamicSharedMemorySize, MM_SMEM);
    cudaFuncSetAttribute(attn_mma,    cudaFuncAttributeMaxDynamicSharedMemorySize, AT_SMEM);

    // 0) convert weights + pos_emb to bf16 hi/lo
    cvt_kernel<<<SZ_1M / 4 / 256, 256>>>(Wq,      wq_h, wq_l, SZ_1M / 4);
    cvt_kernel<<<SZ_1M / 4 / 256, 256>>>(Wk,      wk_h, wk_l, SZ_1M / 4);
    cvt_kernel<<<SZ_1M / 4 / 256, 256>>>(Wv,      wv_h, wv_l, SZ_1M / 4);
    cvt_kernel<<<SZ_1M / 4 / 256, 256>>>(proj_w,  pw_h, pw_l, SZ_1M / 4);
    cvt_kernel<<<SZ_4M / 4 / 256, 256>>>(w1_w,    w1h,  w1l,  SZ_4M / 4);
    cvt_kernel<<<SZ_4M / 4 / 256, 256>>>(w2_w,    w2h,  w2l,  SZ_4M / 4);
    cvt_kernel<<<SZ_4M / 4 / 256, 256>>>(w3_w,    w3h,  w3l,  SZ_4M / 4);
    cvt_kernel<<<SZ_2M / 4 / 256, 256>>>(pos_emb, pe_h, pe_l, SZ_2M / 4);

    // 1) gated rmsnorm -> xn (bf16 hi/lo)
    rms_kernel<<<4096, 256>>>(x, x_token, lcw, n1w, xn_h, xn_l, 1);
    // 2) q (scaled by D^-0.5), k, v -> bf16 hi/lo (EPI 4)
    mma_gemm<4><<<dim3(8, 32), 512, MM_SMEM>>>(xn_h, xn_l, wq_h, wq_l, nullptr, nullptr, nullptr, q_h, q_l, 4096, 1024, 1024, 0.03125f);
    mma_gemm<4><<<dim3(8, 16), 512, MM_SMEM>>>(pe_h, pe_l, wk_h, wk_l, nullptr, nullptr, nullptr, k_h, k_l, 2048, 1024, 1024, 1.0f);
    mma_gemm<4><<<dim3(8, 32), 512, MM_SMEM>>>(xn_h, xn_l, wv_h, wv_l, nullptr, nullptr, nullptr, v_h, v_l, 4096, 1024, 1024, 1.0f);
    // 3) tensor-core causal attention -> at (bf16 hi/lo)
    attn_mma<<<dim3(16, 16, 2), 128, AT_SMEM>>>(q_h, q_l, k_h, k_l, v_h, v_l, at_h, at_l);
    // 4) x_mid = x + attn @ proj_w^T + proj_b  (fp32)
    mma_gemm<1><<<dim3(8, 32), 512, MM_SMEM>>>(at_h, at_l, pw_h, pw_l, proj_b, x, xm, nullptr, nullptr, 4096, 1024, 1024, 1.0f);
    // 5) xn2 = rmsnorm(x_mid) -> xn (bf16 hi/lo)
    rms_kernel<<<4096, 256>>>(xm, nullptr, nullptr, n2w, xn_h, xn_l, 0);
    // 6) h1 = xn2 @ w1^T + b1 (fp32) ; h = silu(h1)*(xn2 @ w3^T + b3) -> bf16
    mma_gemm<2><<<dim3(32, 32), 512, MM_SMEM>>>(xn_h, xn_l, w1h, w1l, w1_b, nullptr, h1, nullptr, nullptr, 4096, 4096, 1024, 1.0f);
    mma_gemm<3><<<dim3(32, 32), 512, MM_SMEM>>>(xn_h, xn_l, w3h, w3l, w3_b, h1, nullptr, h_h, h_l, 4096, 4096, 1024, 1.0f);
    // 7) out = x_mid + h @ w2^T + b2  (fp32)
    mma_gemm<1><<<dim3(8, 32), 512, MM_SMEM>>>(h_h, h_l, w2h, w2l, w2_b, xm, out, nullptr, nullptr, 4096, 1024, 4096, 1.0f);
}

// round 16
// speedup vs baseline: 1.6500x; 1.0180x over previous
#include <cuda_runtime.h>
#include <cuda_bf16.h>
#include <cstdint>
#include <cstddef>

// ---------------------------------------------------------------------------
// Scratch (static __device__ arrays; no allocation anywhere)
// ---------------------------------------------------------------------------
__device__ float g_xm[4096 * 1024];     // x + attn proj (residual mid)
__device__ float g_h1[4096 * 4096];     // FFN pre-gate (w1 out), fp32

// bf16 hi/lo pool: for each tensor, [hi | lo] contiguous
#define SZ_1M  1048576
#define SZ_2M  2097152
#define SZ_4M  4194304
#define SZ_16M 16777216
#define O_WQ 0
#define O_WK (O_WQ + 2 * SZ_1M)
#define O_WV (O_WK + 2 * SZ_1M)
#define O_PW (O_WV + 2 * SZ_1M)
#define O_W1 (O_PW + 2 * SZ_1M)
#define O_W2 (O_W1 + 2 * SZ_4M)
#define O_W3 (O_W2 + 2 * SZ_4M)
#define O_PE (O_W3 + 2 * SZ_4M)
#define O_XN (O_PE + 2 * SZ_2M)
#define O_AT (O_XN + 2 * SZ_4M)
#define O_H  (O_AT + 2 * SZ_4M)
#define O_QB (O_H  + 2 * SZ_16M)
#define O_KB (O_QB + 2 * SZ_4M)
#define O_VB (O_KB + 2 * SZ_2M)
#define BF_TOTAL (O_VB + 2 * SZ_4M)
__device__ __nv_bfloat16 g_bf[BF_TOTAL];

// ---------------------------------------------------------------------------
// helpers
// ---------------------------------------------------------------------------
__device__ __forceinline__ float siluf(float z) { return z / (1.0f + expf(-z)); }

__device__ __forceinline__ void wr_hilo2(__nv_bfloat16* H, __nv_bfloat16* L,
                                         size_t p, float a, float b) {
    __nv_bfloat16 ha = __float2bfloat16(a), hb = __float2bfloat16(b);
    __nv_bfloat16 la = __float2bfloat16(a - __bfloat162float(ha));
    __nv_bfloat16 lb = __float2bfloat16(b - __bfloat162float(hb));
    *(uint32_t*)(H + p) = (uint32_t)__bfloat16_as_ushort(ha) |
                          ((uint32_t)__bfloat16_as_ushort(hb) << 16);
    *(uint32_t*)(L + p) = (uint32_t)__bfloat16_as_ushort(la) |
                          ((uint32_t)__bfloat16_as_ushort(lb) << 16);
}
__device__ __forceinline__ void wr_hilo4(__nv_bfloat16* H, __nv_bfloat16* L,
                                         size_t p, float4 v) {
    __nv_bfloat16 h0 = __float2bfloat16(v.x), h1 = __float2bfloat16(v.y),
                  h2 = __float2bfloat16(v.z), h3 = __float2bfloat16(v.w);
    __nv_bfloat16 l0 = __float2bfloat16(v.x - __bfloat162float(h0));
    __nv_bfloat16 l1 = __float2bfloat16(v.y - __bfloat162float(h1));
    __nv_bfloat16 l2 = __float2bfloat16(v.z - __bfloat162float(h2));
    __nv_bfloat16 l3 = __float2bfloat16(v.w - __bfloat162float(h3));
    uint2 hp, lp;
    hp.x = (uint32_t)__bfloat16_as_ushort(h0) | ((uint32_t)__bfloat16_as_ushort(h1) << 16);
    hp.y = (uint32_t)__bfloat16_as_ushort(h2) | ((uint32_t)__bfloat16_as_ushort(h3) << 16);
    lp.x = (uint32_t)__bfloat16_as_ushort(l0) | ((uint32_t)__bfloat16_as_ushort(l1) << 16);
    lp.y = (uint32_t)__bfloat16_as_ushort(l2) | ((uint32_t)__bfloat16_as_ushort(l3) << 16);
    *(uint2*)(H + p) = hp;
    *(uint2*)(L + p) = lp;
}

__device__ __forceinline__ uint32_t smem_u32(const void* p) {
    uint32_t a;
    asm("{ .reg .u64 t; cvta.to.shared.u64 t, %1; cvt.u32.u64 %0, t; }"
        : "=r"(a) : "l"(p));
    return a;
}
__device__ __forceinline__ void ldmx4(uint32_t* r, uint32_t addr) {
    asm volatile("ldmatrix.sync.aligned.m8n8.x4.shared.b16 {%0,%1,%2,%3}, [%4];"
                 : "=r"(r[0]), "=r"(r[1]), "=r"(r[2]), "=r"(r[3]) : "r"(addr));
}
__device__ __forceinline__ void ldmx4t(uint32_t* r, uint32_t addr) {
    asm volatile("ldmatrix.sync.aligned.m8n8.x4.trans.shared.b16 {%0,%1,%2,%3}, [%4];"
                 : "=r"(r[0]), "=r"(r[1]), "=r"(r[2]), "=r"(r[3]) : "r"(addr));
}
__device__ __forceinline__ void mma16816(float* d, const uint32_t* a,
                                         const uint32_t* b) {
    asm volatile(
        "mma.sync.aligned.m16n8k16.row.col.f32.bf16.bf16.f32 "
        "{%0,%1,%2,%3}, {%4,%5,%6,%7}, {%8,%9}, {%0,%1,%2,%3};"
        : "+f"(d[0]), "+f"(d[1]), "+f"(d[2]), "+f"(d[3])
        : "r"(a[0]), "r"(a[1]), "r"(a[2]), "r"(a[3]), "r"(b[0]), "r"(b[1]));
}
__device__ __forceinline__ void cp16(uint32_t dst, const void* src) {
    asm volatile("cp.async.cg.shared.global [%0], [%1], 16;"
                 :: "r"(dst), "l"(src) : "memory");
}
__device__ __forceinline__ void cp_commit() {
    asm volatile("cp.async.commit_group;" ::: "memory");
}
__device__ __forceinline__ void cp_wait0() {
    asm volatile("cp.async.wait_group 0;" ::: "memory");
}
__device__ __forceinline__ void cp_wait1() {
    asm volatile("cp.async.wait_group 1;" ::: "memory");
}

// ---------------------------------------------------------------------------
// GEMM core (device): C[M,N] = A[M,K]*B[N,K]^T, bf16 hi/lo operands in GMEM.
// 3-term: Ah*Bh + Ah*Bl + Al*Bh. 128x128x64 tile, 512 threads, 3-stage
// cp.async, ONE barrier per chunk (issue for c+2 is safe right after the
// barrier: it overwrites the stage last read in chunk c-1).
// EPI: 0 fp32 | 1 res+acc+bias fp32 | 2 acc+bias fp32
//      3 silu(res)*(acc+bias)->bf16 hi/lo | 4 acc*sc -> bf16 hi/lo
// ---------------------------------------------------------------------------
#define MBM 128
#define MBN 128
#define MBK 64
#define STAGE 65536
#define NSTAGE 3
#define MM_SMEM (NSTAGE * STAGE)

template <int EPI>
__device__ __forceinline__
void gemm_core(const __nv_bfloat16* __restrict__ Ah, const __nv_bfloat16* __restrict__ Al,
               const __nv_bfloat16* __restrict__ Bh, const __nv_bfloat16* __restrict__ Bl,
               const float* __restrict__ bias, const float* __restrict__ res,
               float* __restrict__ C, __nv_bfloat16* __restrict__ Oh,
               __nv_bfloat16* __restrict__ Ol, int M, int N, int K, float sc,
               char* smem)
{
    const uint32_t smem_b = smem_u32(smem);
    const int tid = threadIdx.x;
    const int wid = tid >> 5;
    const int lid = tid & 31;
    const int warp_m = wid >> 2;
    const int warp_n = wid & 3;
    const int bm = blockIdx.y * MBM;
    const int bn = blockIdx.x * MBN;

    const int g   = lid >> 2;
    const int tig = lid & 3;
    const int mat = lid >> 3;
    const int rwi = lid & 7;

    const int rowA_base = warp_m * 32 + rwi + (mat & 1) * 8;
    const int khA       = mat >> 1;
    const int rowB_base = warp_n * 32 + (mat >> 1) * 8 + rwi;
    const int khB       = mat & 1;

    float acc[2][4][4];
#pragma unroll
    for (int i = 0; i < 2; ++i)
#pragma unroll
        for (int j = 0; j < 4; ++j)
#pragma unroll
            for (int q = 0; q < 4; ++q) acc[i][j][q] = 0.0f;

    const __nv_bfloat16* Ahb = Ah + (size_t)bm * K;
    const __nv_bfloat16* Alb = Al + (size_t)bm * K;
    const __nv_bfloat16* Bhb = Bh + (size_t)bn * K;
    const __nv_bfloat16* Blb = Bl + (size_t)bn * K;
    const int nchunks = K / MBK;

    const int lrow_lo = tid >> 3;
    const int lch     = tid & 7;

    auto issue = [&](int kc, int stage) {
        const uint32_t sb2 = smem_b + stage * STAGE;
        const size_t koff = (size_t)kc * MBK + lch * 8;
#pragma unroll
        for (int i = 0; i < 8; ++i) {
            const int comp = i >> 1;
            const int row  = lrow_lo + (i & 1) * 64;
            const uint32_t sw16 = (uint32_t)(((lch ^ (row & 7)) << 4));
            uint32_t dst;
            const __nv_bfloat16* src;
            if (comp == 0)      { dst = sb2 + row * 256 + sw16;               src = Ahb + (size_t)row * K + koff; }
            else if (comp == 1) { dst = sb2 + row * 256 + 128 + sw16;         src = Alb + (size_t)row * K + koff; }
            else if (comp == 2) { dst = sb2 + 32768 + row * 256 + sw16;       src = Bhb + (size_t)row * K + koff; }
            else                { dst = sb2 + 32768 + row * 256 + 128 + sw16; src = Blb + (size_t)row * K + koff; }
            cp16(dst, src);
        }
        cp_commit();
    };

    issue(0, 0);
    if (nchunks > 1) issue(1, 1);

    int buf = 0;
    for (int c = 0; c < nchunks; ++c) {
        if (c + 1 < nchunks) cp_wait1(); else cp_wait0();
        __syncthreads();
        // safe: stage (c+2)%3 was last read in chunk c-1, finished before this barrier
        if (c + 2 < nchunks) issue(c + 2, (c + 2) % NSTAGE);

        const uint32_t sa_u = smem_b + buf * STAGE;
        const uint32_t sb_u = sa_u + 32768;
#pragma unroll
        for (int ks = 0; ks < 4; ++ks) {
            uint32_t ah[2][4], al[2][4], bh[2][4], bl[2][4];
#pragma unroll
            for (int am = 0; am < 2; ++am) {
                int row = rowA_base + am * 16;
                uint32_t sw16 = (((2 * ks + khA) ^ (row & 7)) << 4);
                ldmx4(ah[am], sa_u + row * 256 + sw16);
                ldmx4(al[am], sa_u + row * 256 + 128 + sw16);
            }
#pragma unroll
            for (int pr = 0; pr < 2; ++pr) {
                int row = rowB_base + pr * 16;
                uint32_t sw16 = (((2 * ks + khB) ^ (row & 7)) << 4);
                ldmx4(bh[pr], sb_u + row * 256 + sw16);
                ldmx4(bl[pr], sb_u + row * 256 + 128 + sw16);
            }
#pragma unroll
            for (int am = 0; am < 2; ++am)
#pragma unroll
                for (int an = 0; an < 4; ++an)
                    mma16816(acc[am][an], ah[am], &bh[an >> 1][(an & 1) * 2]);
#pragma unroll
            for (int am = 0; am < 2; ++am)
#pragma unroll
                for (int an = 0; an < 4; ++an)
                    mma16816(acc[am][an], ah[am], &bl[an >> 1][(an & 1) * 2]);
#pragma unroll
            for (int am = 0; am < 2; ++am)
#pragma unroll
                for (int an = 0; an < 4; ++an)
                    mma16816(acc[am][an], al[am], &bh[an >> 1][(an & 1) * 2]);
        }
        buf = (buf + 1) % NSTAGE;
    }

#pragma unroll
    for (int am = 0; am < 2; ++am) {
        const int row0 = bm + warp_m * 32 + am * 16 + g;
#pragma unroll
        for (int an = 0; an < 4; ++an) {
            const int col = bn + warp_n * 32 + an * 8 + tig * 2;
            const float* d = acc[am][an];
            float2 o0 = make_float2(d[0], d[1]);
            float2 o1 = make_float2(d[2], d[3]);
            const size_t p0 = (size_t)row0 * N + col;
            const size_t p1 = (size_t)(row0 + 8) * N + col;
            if (EPI == 0) {
                *(float2*)(C + p0) = o0;
                *(float2*)(C + p1) = o1;
            } else if (EPI == 1) {
                float2 b2 = *(const float2*)(bias + col);
                float2 r0 = *(const float2*)(res + p0);
                float2 r1 = *(const float2*)(res + p1);
                o0.x += b2.x + r0.x; o0.y += b2.y + r0.y;
                o1.x += b2.x + r1.x; o1.y += b2.y + r1.y;
                *(float2*)(C + p0) = o0;
                *(float2*)(C + p1) = o1;
            } else if (EPI == 2) {
                float2 b2 = *(const float2*)(bias + col);
                o0.x += b2.x; o0.y += b2.y;
                o1.x += b2.x; o1.y += b2.y;
                *(float2*)(C + p0) = o0;
                *(float2*)(C + p1) = o1;
            } else if (EPI == 3) {
                float2 b2 = *(const float2*)(bias + col);
                float2 g0 = *(const float2*)(res + p0);
                float2 g1 = *(const float2*)(res + p1);
                o0.x = siluf(g0.x) * (o0.x + b2.x);
                o0.y = siluf(g0.y) * (o0.y + b2.y);
                o1.x = siluf(g1.x) * (o1.x + b2.x);
                o1.y = siluf(g1.y) * (o1.y + b2.y);
                wr_hilo2(Oh, Ol, p0, o0.x, o0.y);
                wr_hilo2(Oh, Ol, p1, o1.x, o1.y);
            } else {
                o0.x *= sc; o0.y *= sc; o1.x *= sc; o1.y *= sc;
                wr_hilo2(Oh, Ol, p0, o0.x, o0.y);
                wr_hilo2(Oh, Ol, p1, o1.x, o1.y);
            }
        }
    }
}

template <int EPI>
__global__ __launch_bounds__(512)
void mma_gemm(const __nv_bfloat16* __restrict__ Ah, const __nv_bfloat16* __restrict__ Al,
              const __nv_bfloat16* __restrict__ Bh, const __nv_bfloat16* __restrict__ Bl,
              const float* __restrict__ bias, const float* __restrict__ res,
              float* __restrict__ C, __nv_bfloat16* __restrict__ Oh,
              __nv_bfloat16* __restrict__ Ol, int M, int N, int K, float sc)
{
    extern __shared__ char smem[];
    gemm_core<EPI>(Ah, Al, Bh, Bl, bias, res, C, Oh, Ol, M, N, K, sc, smem);
}

// Fused q/k/v projection: blockIdx.z selects {q, k, v}. One launch, 640 CTAs.
struct QKVArgs {
    const __nv_bfloat16 *xnh, *xnl, *peh, *pel;
    const __nv_bfloat16 *wqh, *wql, *wkh, *wkl, *wvh, *wvl;
    __nv_bfloat16 *qh, *ql, *kh, *kl, *vh, *vl;
};

__global__ __launch_bounds__(512)
void qkv_gemm(QKVArgs a)
{
    extern __shared__ char smem[];
    const int z = blockIdx.z;
    if (z == 1 && blockIdx.y >= 16) return;   // k has M=2048 only
    const __nv_bfloat16 *Ah, *Al, *Bh, *Bl;
    __nv_bfloat16 *Oh, *Ol;
    float sc;
    if (z == 0)      { Ah = a.xnh; Al = a.xnl; Bh = a.wqh; Bl = a.wql; Oh = a.qh; Ol = a.ql; sc = 0.03125f; }
    else if (z == 1) { Ah = a.peh; Al = a.pel; Bh = a.wkh; Bl = a.wkl; Oh = a.kh; Ol = a.kl; sc = 1.0f; }
    else             { Ah = a.xnh; Al = a.xnl; Bh = a.wvh; Bl = a.wvl; Oh = a.vh; Ol = a.vl; sc = 1.0f; }
    gemm_core<4>(Ah, Al, Bh, Bl, nullptr, nullptr, nullptr, Oh, Ol,
                 4096, 1024, 1024, sc, smem);
}

// ---------------------------------------------------------------------------
// fp32 -> bf16 hi/lo conversion (weights, pos_emb)
// ---------------------------------------------------------------------------
__global__ __launch_bounds__(256)
void cvt_kernel(const float* __restrict__ src, __nv_bfloat16* __restrict__ hi,
                __nv_bfloat16* __restrict__ lo, int n4)
{
    int i = blockIdx.x * blockDim.x + threadIdx.x;
    if (i >= n4) return;
    float4 v = ((const float4*)src)[i];
    wr_hilo4(hi, lo, (size_t)i * 4, v);
}

// ---------------------------------------------------------------------------
// RMSNorm -> bf16 hi/lo (optionally sigmoid-gated blend of x and x_token)
// ---------------------------------------------------------------------------
__global__ __launch_bounds__(256)
void rms_kernel(const float* __restrict__ X, const float* __restrict__ XT,
                const float* __restrict__ lcw, const float* __restrict__ W,
                __nv_bfloat16* __restrict__ Oh, __nv_bfloat16* __restrict__ Ol,
                int gated)
{
    const int row = blockIdx.x;
    const int tid = threadIdx.x;
    float4 xv = ((const float4*)(X + (size_t)row * 1024))[tid];
    if (gated) {
        float lc = 1.0f / (1.0f + expf(-lcw[0]));
        float om = 1.0f - lc;
        float4 tv = ((const float4*)(XT + (size_t)row * 1024))[tid];
        xv.x = lc * xv.x + om * tv.x;
        xv.y = lc * xv.y + om * tv.y;
        xv.z = lc * xv.z + om * tv.z;
        xv.w = lc * xv.w + om * tv.w;
    }
    float ss = xv.x * xv.x + xv.y * xv.y + xv.z * xv.z + xv.w * xv.w;
#pragma unroll
    for (int o = 16; o > 0; o >>= 1) ss += __shfl_xor_sync(0xffffffffu, ss, o);
    __shared__ float red[8];
    if ((tid & 31) == 0) red[tid >> 5] = ss;
    __syncthreads();
    float tot = red[0] + red[1] + red[2] + red[3] + red[4] + red[5] + red[6] + red[7];
    float rinv = rsqrtf(tot * (1.0f / 1024.0f) + 1e-5f);
    float4 wv = ((const float4*)W)[tid];
    float4 ov;
    ov.x = xv.x * rinv * wv.x;
    ov.y = xv.y * rinv * wv.y;
    ov.z = xv.z * rinv * wv.z;
    ov.w = xv.w * rinv * wv.w;
    wr_hilo4(Oh, Ol, (size_t)row * 1024 + tid * 4, ov);
}

// ---------------------------------------------------------------------------
// Tensor-core causal flash attention (R15 version, known good).
// Block = (128 q rows, head h, batch b), 128 threads = 4 warps.
// smem: Q 32K | K 16K | V 16K | P 32K = 96KB -> 2 blocks/SM.
// ---------------------------------------------------------------------------
#define AT_SMEM 98304

__global__ __launch_bounds__(128, 2)
void attn_mma(const __nv_bfloat16* __restrict__ Qh, const __nv_bfloat16* __restrict__ Ql,
              const __nv_bfloat16* __restrict__ Kh, const __nv_bfloat16* __restrict__ Kl,
              const __nv_bfloat16* __restrict__ Vh, const __nv_bfloat16* __restrict__ Vl,
              __nv_bfloat16* __restrict__ Oh, __nv_bfloat16* __restrict__ Ol)
{
    extern __shared__ char smem[];
    const uint32_t sb = smem_u32(smem);
    const int qt = blockIdx.x, h = blockIdx.y, b = blockIdx.z;
    const int q0 = qt * 128;
    const int tid = threadIdx.x;
    const int wid = tid >> 5;
    const int lid = tid & 31;
    const int g = lid >> 2, tig = lid & 3;
    const int mat = lid >> 3, rwi = lid & 7;
    const uint32_t AQ = sb, AK = sb + 32768, AV = sb + 49152, AP = sb + 65536;
    const float NEGINF = __int_as_float(0xff800000);

    {
        const int row = tid;
        const size_t gq = ((size_t)(b * 2048 + q0 + row)) * 1024 + h * 64;
#pragma unroll
        for (int cc = 0; cc < 8; ++cc) {
            const uint32_t sw = (uint32_t)(((cc ^ (row & 7)) << 4));
            cp16(AQ + row * 256 + sw,       Qh + gq + cc * 8);
            cp16(AQ + row * 256 + 128 + sw, Ql + gq + cc * 8);
        }
        cp_commit();
    }

    float oacc[2][8][4];
#pragma unroll
    for (int i = 0; i < 2; ++i)
#pragma unroll
        for (int j = 0; j < 8; ++j)
#pragma unroll
            for (int q = 0; q < 4; ++q) oacc[i][j][q] = 0.0f;
    float mrow[4], lrow[4];
#pragma unroll
    for (int i = 0; i < 4; ++i) { mrow[i] = NEGINF; lrow[i] = 0.0f; }

    const int ntiles = qt * 2 + 2;
    for (int t = 0; t < ntiles; ++t) {
        const int kt = t * 64;
        {
            const int row = tid >> 1;
            const int isv = tid & 1;
            const size_t gk = (size_t)(kt + row) * 1024 + h * 64;
            const size_t gv = ((size_t)(b * 2048 + kt + row)) * 1024 + h * 64;
            const __nv_bfloat16* sh = isv ? (Vh + gv) : (Kh + gk);
            const __nv_bfloat16* sl = isv ? (Vl + gv) : (Kl + gk);
            const uint32_t dstb = (isv ? AV : AK) + row * 256;
#pragma unroll
            for (int cc = 0; cc < 8; ++cc) {
                const uint32_t sw = (uint32_t)(((cc ^ (row & 7)) << 4));
                cp16(dstb + sw,       sh + cc * 8);
                cp16(dstb + 128 + sw, sl + cc * 8);
            }
            cp_commit();
        }
        cp_wait0();
        __syncthreads();

        // ---- S = Q K^T (3-term) ----
        float sacc[2][8][4];
#pragma unroll
        for (int i = 0; i < 2; ++i)
#pragma unroll
            for (int j = 0; j < 8; ++j)
#pragma unroll
                for (int q = 0; q < 4; ++q) sacc[i][j][q] = 0.0f;
#pragma unroll
        for (int ks = 0; ks < 4; ++ks) {
            uint32_t qh2[2][4], ql2[2][4], kh2[4][4], kl2[4][4];
#pragma unroll
            for (int am = 0; am < 2; ++am) {
                const int row = wid * 32 + am * 16 + rwi + (mat & 1) * 8;
                const uint32_t sw = (uint32_t)((((2 * ks + (mat >> 1)) ^ (row & 7)) << 4));
                ldmx4(qh2[am], AQ + row * 256 + sw);
                ldmx4(ql2[am], AQ + row * 256 + 128 + sw);
            }
#pragma unroll
            for (int pr = 0; pr < 4; ++pr) {
                const int row = pr * 16 + (mat >> 1) * 8 + rwi;
                const uint32_t sw = (uint32_t)((((2 * ks + (mat & 1)) ^ (row & 7)) << 4));
                ldmx4(kh2[pr], AK + row * 256 + sw);
                ldmx4(kl2[pr], AK + row * 256 + 128 + sw);
            }
#pragma unroll
            for (int am = 0; am < 2; ++am)
#pragma unroll
                for (int an = 0; an < 8; ++an)
                    mma16816(sacc[am][an], qh2[am], &kh2[an >> 1][(an & 1) * 2]);
#pragma unroll
            for (int am = 0; am < 2; ++am)
#pragma unroll
                for (int an = 0; an < 8; ++an)
                    mma16816(sacc[am][an], qh2[am], &kl2[an >> 1][(an & 1) * 2]);
#pragma unroll
            for (int am = 0; am < 2; ++am)
#pragma unroll
                for (int an = 0; an < 8; ++an)
                    mma16816(sacc[am][an], ql2[am], &kh2[an >> 1][(an & 1) * 2]);
        }

        // ---- online softmax per row-slot ----
        const bool need_mask = (kt + 63 > q0 + wid * 32);
#pragma unroll
        for (int rs = 0; rs < 4; ++rs) {
            const int am = rs >> 1, hh = rs & 1;
            const int prow = wid * 32 + am * 16 + g + 8 * hh;
            const int row_g = q0 + prow;
            float v16[16];
#pragma unroll
            for (int an = 0; an < 8; ++an) {
                v16[an * 2]     = sacc[am][an][hh * 2];
                v16[an * 2 + 1] = sacc[am][an][hh * 2 + 1];
            }
            if (need_mask) {
#pragma unroll
                for (int an = 0; an < 8; ++an) {
                    const int c0 = kt + an * 8 + tig * 2;
                    if (c0 > row_g)     v16[an * 2]     = NEGINF;
                    if (c0 + 1 > row_g) v16[an * 2 + 1] = NEGINF;
                }
            }
            float rmax = v16[0];
#pragma unroll
            for (int i = 1; i < 16; ++i) rmax = fmaxf(rmax, v16[i]);
            rmax = fmaxf(rmax, __shfl_xor_sync(0xffffffffu, rmax, 1));
            rmax = fmaxf(rmax, __shfl_xor_sync(0xffffffffu, rmax, 2));
            const float mn = fmaxf(mrow[rs], rmax);
            const float f = __expf(mrow[rs] - mn);
            mrow[rs] = mn;
            float sum = 0.0f;
#pragma unroll
            for (int i = 0; i < 16; ++i) { v16[i] = __expf(v16[i] - mn); sum += v16[i]; }
            sum += __shfl_xor_sync(0xffffffffu, sum, 1);
            sum += __shfl_xor_sync(0xffffffffu, sum, 2);
            lrow[rs] = lrow[rs] * f + sum;
#pragma unroll
            for (int an = 0; an < 8; ++an) {
                oacc[am][an][hh * 2]     *= f;
                oacc[am][an][hh * 2 + 1] *= f;
            }
            const uint32_t pb = AP + prow * 256 + tig * 4;
#pragma unroll
            for (int an = 0; an < 8; ++an) {
                const uint32_t sw = (uint32_t)(((an ^ (prow & 7)) << 4));
                float a = v16[an * 2], b2 = v16[an * 2 + 1];
                __nv_bfloat16 ha = __float2bfloat16(a), hb = __float2bfloat16(b2);
                __nv_bfloat16 la = __float2bfloat16(a - __bfloat162float(ha));
                __nv_bfloat16 lb = __float2bfloat16(b2 - __bfloat162float(hb));
                uint32_t hw = (uint32_t)__bfloat16_as_ushort(ha) |
                              ((uint32_t)__bfloat16_as_ushort(hb) << 16);
                uint32_t lw = (uint32_t)__bfloat16_as_ushort(la) |
                              ((uint32_t)__bfloat16_as_ushort(lb) << 16);
                asm volatile("st.shared.b32 [%0], %1;" :: "r"(pb + sw), "r"(hw));
                asm volatile("st.shared.b32 [%0], %1;" :: "r"(pb + 128 + sw), "r"(lw));
            }
        }
        __syncwarp();

        // ---- O += P V (3-term, V via trans-ldmatrix) ----
#pragma unroll
        for (int ks = 0; ks < 4; ++ks) {
            uint32_t ph2[2][4], pl2[2][4], vh2[4][4], vl2[4][4];
#pragma unroll
            for (int am = 0; am < 2; ++am) {
                const int row = wid * 32 + am * 16 + rwi + (mat & 1) * 8;
                const uint32_t sw = (uint32_t)((((2 * ks + (mat >> 1)) ^ (row & 7)) << 4));
                ldmx4(ph2[am], AP + row * 256 + sw);
                ldmx4(pl2[am], AP + row * 256 + 128 + sw);
            }
#pragma unroll
            for (int pr = 0; pr < 4; ++pr) {
                const int row = ks * 16 + (mat & 1) * 8 + rwi;
                const uint32_t sw = (uint32_t)((((pr * 2 + (mat >> 1)) ^ (row & 7)) << 4));
                ldmx4t(vh2[pr], AV + row * 256 + sw);
                ldmx4t(vl2[pr], AV + row * 256 + 128 + sw);
            }
#pragma unroll
            for (int am = 0; am < 2; ++am)
#pragma unroll
                for (int an = 0; an < 8; ++an)
                    mma16816(oacc[am][an], ph2[am], &vh2[an >> 1][(an & 1) * 2]);
#pragma unroll
            for (int am = 0; am < 2; ++am)
#pragma unroll
                for (int an = 0; an < 8; ++an)
                    mma16816(oacc[am][an], ph2[am], &vl2[an >> 1][(an & 1) * 2]);
#pragma unroll
            for (int am = 0; am < 2; ++am)
#pragma unroll
                for (int an = 0; an < 8; ++an)
                    mma16816(oacc[am][an], pl2[am], &vh2[an >> 1][(an & 1) * 2]);
        }
        __syncthreads();
    }

#pragma unroll
    for (int rs = 0; rs < 4; ++rs) {
        const int am = rs >> 1, hh = rs & 1;
        const int prow = wid * 32 + am * 16 + g + 8 * hh;
        const float inv = 1.0f / lrow[rs];
        const size_t gb = ((size_t)(b * 2048 + q0 + prow)) * 1024 + h * 64;
#pragma unroll
        for (int an = 0; an < 8; ++an) {
            const int col = an * 8 + tig * 2;
            wr_hilo2(Oh, Ol, gb + col,
                     oacc[am][an][hh * 2] * inv, oacc[am][an][hh * 2 + 1] * inv);
        }
    }
}

// ---------------------------------------------------------------------------
// Launch
// ---------------------------------------------------------------------------
extern "C" void kernel_launch(void* const* d_in, const int* in_sizes, int n_in,
                              void* d_out, int out_size)
{
    const float* x       = (const float*)d_in[0];
    const float* x_token = (const float*)d_in[1];
    const float* pos_emb = (const float*)d_in[2];
    const float* lcw     = (const float*)d_in[3];
    const float* Wq      = (const float*)d_in[4];
    const float* Wk      = (const float*)d_in[5];
    const float* Wv      = (const float*)d_in[6];
    const float* proj_w  = (const float*)d_in[7];
    const float* proj_b  = (const float*)d_in[8];
    const float* w1_w    = (const float*)d_in[9];
    const float* w1_b    = (const float*)d_in[10];
    const float* w2_w    = (const float*)d_in[11];
    const float* w2_b    = (const float*)d_in[12];
    const float* w3_w    = (const float*)d_in[13];
    const float* w3_b    = (const float*)d_in[14];
    const float* n1w     = (const float*)d_in[15];
    const float* n2w     = (const float*)d_in[16];
    float* out = (float*)d_out;

    float *xm, *h1;
    __nv_bfloat16* bf;
    cudaGetSymbolAddress((void**)&xm, g_xm);
    cudaGetSymbolAddress((void**)&h1, g_h1);
    cudaGetSymbolAddress((void**)&bf, g_bf);

    __nv_bfloat16 *wq_h = bf + O_WQ, *wq_l = wq_h + SZ_1M;
    __nv_bfloat16 *wk_h = bf + O_WK, *wk_l = wk_h + SZ_1M;
    __nv_bfloat16 *wv_h = bf + O_WV, *wv_l = wv_h + SZ_1M;
    __nv_bfloat16 *pw_h = bf + O_PW, *pw_l = pw_h + SZ_1M;
    __nv_bfloat16 *w1h  = bf + O_W1, *w1l  = w1h + SZ_4M;
    __nv_bfloat16 *w2h  = bf + O_W2, *w2l  = w2h + SZ_4M;
    __nv_bfloat16 *w3h  = bf + O_W3, *w3l  = w3h + SZ_4M;
    __nv_bfloat16 *pe_h = bf + O_PE, *pe_l = pe_h + SZ_2M;
    __nv_bfloat16 *xn_h = bf + O_XN, *xn_l = xn_h + SZ_4M;
    __nv_bfloat16 *at_h = bf + O_AT, *at_l = at_h + SZ_4M;
    __nv_bfloat16 *h_h  = bf + O_H,  *h_l  = h_h + SZ_16M;
    __nv_bfloat16 *q_h  = bf + O_QB, *q_l  = q_h + SZ_4M;
    __nv_bfloat16 *k_h  = bf + O_KB, *k_l  = k_h + SZ_2M;
    __nv_bfloat16 *v_h  = bf + O_VB, *v_l  = v_h + SZ_4M;

    cudaFuncSetAttribute(mma_gemm<1>, cudaFuncAttributeMaxDynamicSharedMemorySize, MM_SMEM);
    cudaFuncSetAttribute(mma_gemm<2>, cudaFuncAttributeMaxDynamicSharedMemorySize, MM_SMEM);
    cudaFuncSetAttribute(mma_gemm<3>, cudaFuncAttributeMaxDynamicSharedMemorySize, MM_SMEM);
    cudaFuncSetAttribute(qkv_gemm,    cudaFuncAttributeMaxDynamicSharedMemorySize, MM_SMEM);
    cudaFuncSetAttribute(attn_mma,    cudaFuncAttributeMaxDynamicSharedMemorySize, AT_SMEM);

    // 0) convert weights + pos_emb to bf16 hi/lo
    cvt_kernel<<<SZ_1M / 4 / 256, 256>>>(Wq,      wq_h, wq_l, SZ_1M / 4);
    cvt_kernel<<<SZ_1M / 4 / 256, 256>>>(Wk,      wk_h, wk_l, SZ_1M / 4);
    cvt_kernel<<<SZ_1M / 4 / 256, 256>>>(Wv,      wv_h, wv_l, SZ_1M / 4);
    cvt_kernel<<<SZ_1M / 4 / 256, 256>>>(proj_w,  pw_h, pw_l, SZ_1M / 4);
    cvt_kernel<<<SZ_4M / 4 / 256, 256>>>(w1_w,    w1h,  w1l,  SZ_4M / 4);
    cvt_kernel<<<SZ_4M / 4 / 256, 256>>>(w2_w,    w2h,  w2l,  SZ_4M / 4);
    cvt_kernel<<<SZ_4M / 4 / 256, 256>>>(w3_w,    w3h,  w3l,  SZ_4M / 4);
    cvt_kernel<<<SZ_2M / 4 / 256, 256>>>(pos_emb, pe_h, pe_l, SZ_2M / 4);

    // 1) gated rmsnorm -> xn (bf16 hi/lo)
    rms_kernel<<<4096, 256>>>(x, x_token, lcw, n1w, xn_h, xn_l, 1);
    // 2) fused q/k/v projections (one launch, better wave packing)
    QKVArgs qa;
    qa.xnh = xn_h; qa.xnl = xn_l; qa.peh = pe_h; qa.pel = pe_l;
    qa.wqh = wq_h; qa.wql = wq_l; qa.wkh = wk_h; qa.wkl = wk_l;
    qa.wvh = wv_h; qa.wvl = wv_l;
    qa.qh = q_h; qa.ql = q_l; qa.kh = k_h; qa.kl = k_l; qa.vh = v_h; qa.vl = v_l;
    qkv_gemm<<<dim3(8, 32, 3), 512, MM_SMEM>>>(qa);
    // 3) tensor-core causal attention -> at (bf16 hi/lo)
    attn_mma<<<dim3(16, 16, 2), 128, AT_SMEM>>>(q_h, q_l, k_h, k_l, v_h, v_l, at_h, at_l);
    // 4) x_mid = x + attn @ proj_w^T + proj_b  (fp32)
    mma_gemm<1><<<dim3(8, 32), 512, MM_SMEM>>>(at_h, at_l, pw_h, pw_l, proj_b, x, xm, nullptr, nullptr, 4096, 1024, 1024, 1.0f);
    // 5) xn2 = rmsnorm(x_mid) -> xn (bf16 hi/lo)
    rms_kernel<<<4096, 256>>>(xm, nullptr, nullptr, n2w, xn_h, xn_l, 0);
    // 6) h1 = xn2 @ w1^T + b1 (fp32) ; h = silu(h1)*(xn2 @ w3^T + b3) -> bf16
    mma_gemm<2><<<dim3(32, 32), 512, MM_SMEM>>>(xn_h, xn_l, w1h, w1l, w1_b, nullptr, h1, nullptr, nullptr, 4096, 4096, 1024, 1.0f);
    mma_gemm<3><<<dim3(32, 32), 512, MM_SMEM>>>(xn_h, xn_l, w3h, w3l, w3_b, h1, nullptr, h_h, h_l, 4096, 4096, 1024, 1.0f);
    // 7) out = x_mid + h @ w2^T + b2  (fp32)
    mma_gemm<1><<<dim3(8, 32), 512, MM_SMEM>>>(h_h, h_l, w2h, w2l, w2_b, xm, out, nullptr, nullptr, 4096, 1024, 4096, 1.0f);
}

// round 17
// speedup vs baseline: 1.7327x; 1.0501x over previous
#include <cuda_runtime.h>
#include <cuda_bf16.h>
#include <cstdint>
#include <cstddef>

// ---------------------------------------------------------------------------
// Scratch (static __device__ arrays; no allocation anywhere)
// ---------------------------------------------------------------------------
__device__ float g_xm[4096 * 1024];     // x + attn proj (residual mid)

// bf16 hi/lo pool: for each tensor, [hi | lo] contiguous
#define SZ_1M  1048576
#define SZ_2M  2097152
#define SZ_4M  4194304
#define SZ_16M 16777216
#define O_WQ 0
#define O_WK (O_WQ + 2 * SZ_1M)
#define O_WV (O_WK + 2 * SZ_1M)
#define O_PW (O_WV + 2 * SZ_1M)
#define O_W1 (O_PW + 2 * SZ_1M)
#define O_W2 (O_W1 + 2 * SZ_4M)
#define O_W3 (O_W2 + 2 * SZ_4M)
#define O_PE (O_W3 + 2 * SZ_4M)
#define O_XN (O_PE + 2 * SZ_2M)
#define O_AT (O_XN + 2 * SZ_4M)
#define O_H  (O_AT + 2 * SZ_4M)
#define O_QB (O_H  + 2 * SZ_16M)
#define O_KB (O_QB + 2 * SZ_4M)
#define O_VB (O_KB + 2 * SZ_2M)
#define BF_TOTAL (O_VB + 2 * SZ_4M)
__device__ __nv_bfloat16 g_bf[BF_TOTAL];

// ---------------------------------------------------------------------------
// helpers
// ---------------------------------------------------------------------------
__device__ __forceinline__ float siluf(float z) { return z / (1.0f + expf(-z)); }

__device__ __forceinline__ void wr_hilo2(__nv_bfloat16* H, __nv_bfloat16* L,
                                         size_t p, float a, float b) {
    __nv_bfloat16 ha = __float2bfloat16(a), hb = __float2bfloat16(b);
    __nv_bfloat16 la = __float2bfloat16(a - __bfloat162float(ha));
    __nv_bfloat16 lb = __float2bfloat16(b - __bfloat162float(hb));
    *(uint32_t*)(H + p) = (uint32_t)__bfloat16_as_ushort(ha) |
                          ((uint32_t)__bfloat16_as_ushort(hb) << 16);
    *(uint32_t*)(L + p) = (uint32_t)__bfloat16_as_ushort(la) |
                          ((uint32_t)__bfloat16_as_ushort(lb) << 16);
}
__device__ __forceinline__ void wr_hilo4(__nv_bfloat16* H, __nv_bfloat16* L,
                                         size_t p, float4 v) {
    __nv_bfloat16 h0 = __float2bfloat16(v.x), h1 = __float2bfloat16(v.y),
                  h2 = __float2bfloat16(v.z), h3 = __float2bfloat16(v.w);
    __nv_bfloat16 l0 = __float2bfloat16(v.x - __bfloat162float(h0));
    __nv_bfloat16 l1 = __float2bfloat16(v.y - __bfloat162float(h1));
    __nv_bfloat16 l2 = __float2bfloat16(v.z - __bfloat162float(h2));
    __nv_bfloat16 l3 = __float2bfloat16(v.w - __bfloat162float(h3));
    uint2 hp, lp;
    hp.x = (uint32_t)__bfloat16_as_ushort(h0) | ((uint32_t)__bfloat16_as_ushort(h1) << 16);
    hp.y = (uint32_t)__bfloat16_as_ushort(h2) | ((uint32_t)__bfloat16_as_ushort(h3) << 16);
    lp.x = (uint32_t)__bfloat16_as_ushort(l0) | ((uint32_t)__bfloat16_as_ushort(l1) << 16);
    lp.y = (uint32_t)__bfloat16_as_ushort(l2) | ((uint32_t)__bfloat16_as_ushort(l3) << 16);
    *(uint2*)(H + p) = hp;
    *(uint2*)(L + p) = lp;
}

__device__ __forceinline__ uint32_t smem_u32(const void* p) {
    uint32_t a;
    asm("{ .reg .u64 t; cvta.to.shared.u64 t, %1; cvt.u32.u64 %0, t; }"
        : "=r"(a) : "l"(p));
    return a;
}
__device__ __forceinline__ void ldmx4(uint32_t* r, uint32_t addr) {
    asm volatile("ldmatrix.sync.aligned.m8n8.x4.shared.b16 {%0,%1,%2,%3}, [%4];"
                 : "=r"(r[0]), "=r"(r[1]), "=r"(r[2]), "=r"(r[3]) : "r"(addr));
}
__device__ __forceinline__ void ldmx4t(uint32_t* r, uint32_t addr) {
    asm volatile("ldmatrix.sync.aligned.m8n8.x4.trans.shared.b16 {%0,%1,%2,%3}, [%4];"
                 : "=r"(r[0]), "=r"(r[1]), "=r"(r[2]), "=r"(r[3]) : "r"(addr));
}
__device__ __forceinline__ void mma16816(float* d, const uint32_t* a,
                                         const uint32_t* b) {
    asm volatile(
        "mma.sync.aligned.m16n8k16.row.col.f32.bf16.bf16.f32 "
        "{%0,%1,%2,%3}, {%4,%5,%6,%7}, {%8,%9}, {%0,%1,%2,%3};"
        : "+f"(d[0]), "+f"(d[1]), "+f"(d[2]), "+f"(d[3])
        : "r"(a[0]), "r"(a[1]), "r"(a[2]), "r"(a[3]), "r"(b[0]), "r"(b[1]));
}
__device__ __forceinline__ void cp16(uint32_t dst, const void* src) {
    asm volatile("cp.async.cg.shared.global [%0], [%1], 16;"
                 :: "r"(dst), "l"(src) : "memory");
}
__device__ __forceinline__ void cp_commit() {
    asm volatile("cp.async.commit_group;" ::: "memory");
}
__device__ __forceinline__ void cp_wait0() {
    asm volatile("cp.async.wait_group 0;" ::: "memory");
}
__device__ __forceinline__ void cp_wait1() {
    asm volatile("cp.async.wait_group 1;" ::: "memory");
}

// ---------------------------------------------------------------------------
// GEMM core (device): C[M,N] = A[M,K]*B[N,K]^T, bf16 hi/lo operands in GMEM.
// 3-term: Ah*Bh + Ah*Bl + Al*Bh. 128x128x64 tile, 512 threads, 3-stage
// cp.async, one barrier per chunk.
// EPI: 0 fp32 | 1 res+acc+bias fp32 | 2 acc+bias fp32
//      3 silu(res)*(acc+bias)->bf16 hi/lo | 4 acc*sc -> bf16 hi/lo
// ---------------------------------------------------------------------------
#define MBM 128
#define MBN 128
#define MBK 64
#define STAGE 65536
#define NSTAGE 3
#define MM_SMEM (NSTAGE * STAGE)

template <int EPI>
__device__ __forceinline__
void gemm_core(const __nv_bfloat16* __restrict__ Ah, const __nv_bfloat16* __restrict__ Al,
               const __nv_bfloat16* __restrict__ Bh, const __nv_bfloat16* __restrict__ Bl,
               const float* __restrict__ bias, const float* __restrict__ res,
               float* __restrict__ C, __nv_bfloat16* __restrict__ Oh,
               __nv_bfloat16* __restrict__ Ol, int M, int N, int K, float sc,
               char* smem)
{
    const uint32_t smem_b = smem_u32(smem);
    const int tid = threadIdx.x;
    const int wid = tid >> 5;
    const int lid = tid & 31;
    const int warp_m = wid >> 2;
    const int warp_n = wid & 3;
    const int bm = blockIdx.y * MBM;
    const int bn = blockIdx.x * MBN;

    const int g   = lid >> 2;
    const int tig = lid & 3;
    const int mat = lid >> 3;
    const int rwi = lid & 7;

    const int rowA_base = warp_m * 32 + rwi + (mat & 1) * 8;
    const int khA       = mat >> 1;
    const int rowB_base = warp_n * 32 + (mat >> 1) * 8 + rwi;
    const int khB       = mat & 1;

    float acc[2][4][4];
#pragma unroll
    for (int i = 0; i < 2; ++i)
#pragma unroll
        for (int j = 0; j < 4; ++j)
#pragma unroll
            for (int q = 0; q < 4; ++q) acc[i][j][q] = 0.0f;

    const __nv_bfloat16* Ahb = Ah + (size_t)bm * K;
    const __nv_bfloat16* Alb = Al + (size_t)bm * K;
    const __nv_bfloat16* Bhb = Bh + (size_t)bn * K;
    const __nv_bfloat16* Blb = Bl + (size_t)bn * K;
    const int nchunks = K / MBK;

    const int lrow_lo = tid >> 3;
    const int lch     = tid & 7;

    auto issue = [&](int kc, int stage) {
        const uint32_t sb2 = smem_b + stage * STAGE;
        const size_t koff = (size_t)kc * MBK + lch * 8;
#pragma unroll
        for (int i = 0; i < 8; ++i) {
            const int comp = i >> 1;
            const int row  = lrow_lo + (i & 1) * 64;
            const uint32_t sw16 = (uint32_t)(((lch ^ (row & 7)) << 4));
            uint32_t dst;
            const __nv_bfloat16* src;
            if (comp == 0)      { dst = sb2 + row * 256 + sw16;               src = Ahb + (size_t)row * K + koff; }
            else if (comp == 1) { dst = sb2 + row * 256 + 128 + sw16;         src = Alb + (size_t)row * K + koff; }
            else if (comp == 2) { dst = sb2 + 32768 + row * 256 + sw16;       src = Bhb + (size_t)row * K + koff; }
            else                { dst = sb2 + 32768 + row * 256 + 128 + sw16; src = Blb + (size_t)row * K + koff; }
            cp16(dst, src);
        }
        cp_commit();
    };

    issue(0, 0);
    if (nchunks > 1) issue(1, 1);

    int buf = 0;
    for (int c = 0; c < nchunks; ++c) {
        if (c + 1 < nchunks) cp_wait1(); else cp_wait0();
        __syncthreads();
        if (c + 2 < nchunks) issue(c + 2, (c + 2) % NSTAGE);

        const uint32_t sa_u = smem_b + buf * STAGE;
        const uint32_t sb_u = sa_u + 32768;
#pragma unroll
        for (int ks = 0; ks < 4; ++ks) {
            uint32_t ah[2][4], al[2][4], bh[2][4], bl[2][4];
#pragma unroll
            for (int am = 0; am < 2; ++am) {
                int row = rowA_base + am * 16;
                uint32_t sw16 = (((2 * ks + khA) ^ (row & 7)) << 4);
                ldmx4(ah[am], sa_u + row * 256 + sw16);
                ldmx4(al[am], sa_u + row * 256 + 128 + sw16);
            }
#pragma unroll
            for (int pr = 0; pr < 2; ++pr) {
                int row = rowB_base + pr * 16;
                uint32_t sw16 = (((2 * ks + khB) ^ (row & 7)) << 4);
                ldmx4(bh[pr], sb_u + row * 256 + sw16);
                ldmx4(bl[pr], sb_u + row * 256 + 128 + sw16);
            }
#pragma unroll
            for (int am = 0; am < 2; ++am)
#pragma unroll
                for (int an = 0; an < 4; ++an)
                    mma16816(acc[am][an], ah[am], &bh[an >> 1][(an & 1) * 2]);
#pragma unroll
            for (int am = 0; am < 2; ++am)
#pragma unroll
                for (int an = 0; an < 4; ++an)
                    mma16816(acc[am][an], ah[am], &bl[an >> 1][(an & 1) * 2]);
#pragma unroll
            for (int am = 0; am < 2; ++am)
#pragma unroll
                for (int an = 0; an < 4; ++an)
                    mma16816(acc[am][an], al[am], &bh[an >> 1][(an & 1) * 2]);
        }
        buf = (buf + 1) % NSTAGE;
    }

#pragma unroll
    for (int am = 0; am < 2; ++am) {
        const int row0 = bm + warp_m * 32 + am * 16 + g;
#pragma unroll
        for (int an = 0; an < 4; ++an) {
            const int col = bn + warp_n * 32 + an * 8 + tig * 2;
            const float* d = acc[am][an];
            float2 o0 = make_float2(d[0], d[1]);
            float2 o1 = make_float2(d[2], d[3]);
            const size_t p0 = (size_t)row0 * N + col;
            const size_t p1 = (size_t)(row0 + 8) * N + col;
            if (EPI == 0) {
                *(float2*)(C + p0) = o0;
                *(float2*)(C + p1) = o1;
            } else if (EPI == 1) {
                float2 b2 = *(const float2*)(bias + col);
                float2 r0 = *(const float2*)(res + p0);
                float2 r1 = *(const float2*)(res + p1);
                o0.x += b2.x + r0.x; o0.y += b2.y + r0.y;
                o1.x += b2.x + r1.x; o1.y += b2.y + r1.y;
                *(float2*)(C + p0) = o0;
                *(float2*)(C + p1) = o1;
            } else if (EPI == 2) {
                float2 b2 = *(const float2*)(bias + col);
                o0.x += b2.x; o0.y += b2.y;
                o1.x += b2.x; o1.y += b2.y;
                *(float2*)(C + p0) = o0;
                *(float2*)(C + p1) = o1;
            } else if (EPI == 3) {
                float2 b2 = *(const float2*)(bias + col);
                float2 g0 = *(const float2*)(res + p0);
                float2 g1 = *(const float2*)(res + p1);
                o0.x = siluf(g0.x) * (o0.x + b2.x);
                o0.y = siluf(g0.y) * (o0.y + b2.y);
                o1.x = siluf(g1.x) * (o1.x + b2.x);
                o1.y = siluf(g1.y) * (o1.y + b2.y);
                wr_hilo2(Oh, Ol, p0, o0.x, o0.y);
                wr_hilo2(Oh, Ol, p1, o1.x, o1.y);
            } else {
                o0.x *= sc; o0.y *= sc; o1.x *= sc; o1.y *= sc;
                wr_hilo2(Oh, Ol, p0, o0.x, o0.y);
                wr_hilo2(Oh, Ol, p1, o1.x, o1.y);
            }
        }
    }
}

template <int EPI>
__global__ __launch_bounds__(512)
void mma_gemm(const __nv_bfloat16* __restrict__ Ah, const __nv_bfloat16* __restrict__ Al,
              const __nv_bfloat16* __restrict__ Bh, const __nv_bfloat16* __restrict__ Bl,
              const float* __restrict__ bias, const float* __restrict__ res,
              float* __restrict__ C, __nv_bfloat16* __restrict__ Oh,
              __nv_bfloat16* __restrict__ Ol, int M, int N, int K, float sc)
{
    extern __shared__ char smem[];
    gemm_core<EPI>(Ah, Al, Bh, Bl, bias, res, C, Oh, Ol, M, N, K, sc, smem);
}

// Fused q/k/v projection: blockIdx.z selects {q, k, v}.
struct QKVArgs {
    const __nv_bfloat16 *xnh, *xnl, *peh, *pel;
    const __nv_bfloat16 *wqh, *wql, *wkh, *wkl, *wvh, *wvl;
    __nv_bfloat16 *qh, *ql, *kh, *kl, *vh, *vl;
};

__global__ __launch_bounds__(512)
void qkv_gemm(QKVArgs a)
{
    extern __shared__ char smem[];
    const int z = blockIdx.z;
    if (z == 1 && blockIdx.y >= 16) return;   // k has M=2048 only
    const __nv_bfloat16 *Ah, *Al, *Bh, *Bl;
    __nv_bfloat16 *Oh, *Ol;
    float sc;
    if (z == 0)      { Ah = a.xnh; Al = a.xnl; Bh = a.wqh; Bl = a.wql; Oh = a.qh; Ol = a.ql; sc = 0.03125f; }
    else if (z == 1) { Ah = a.peh; Al = a.pel; Bh = a.wkh; Bl = a.wkl; Oh = a.kh; Ol = a.kl; sc = 1.0f; }
    else             { Ah = a.xnh; Al = a.xnl; Bh = a.wvh; Bl = a.wvl; Oh = a.vh; Ol = a.vl; sc = 1.0f; }
    gemm_core<4>(Ah, Al, Bh, Bl, nullptr, nullptr, nullptr, Oh, Ol,
                 4096, 1024, 1024, sc, smem);
}

// ---------------------------------------------------------------------------
// Fused FFN-up: h = silu(xn@W1^T + b1) * (xn@W3^T + b3) -> bf16 hi/lo.
// One CTA computes BOTH w1 and w3 tiles for the same (bm, bn), sharing the
// A (xn) smem tile. h1 never touches gmem. M=4096, N=4096, K=1024.
// smem stage = A 32K + B1 32K + B3 32K = 96KB, 2 stages = 192KB.
// ---------------------------------------------------------------------------
#define F_STAGE 98304
#define FF_SMEM (2 * F_STAGE)

__global__ __launch_bounds__(512)
void ffn_gemm(const __nv_bfloat16* __restrict__ Ah, const __nv_bfloat16* __restrict__ Al,
              const __nv_bfloat16* __restrict__ B1h, const __nv_bfloat16* __restrict__ B1l,
              const __nv_bfloat16* __restrict__ B3h, const __nv_bfloat16* __restrict__ B3l,
              const float* __restrict__ bias1, const float* __restrict__ bias3,
              __nv_bfloat16* __restrict__ Oh, __nv_bfloat16* __restrict__ Ol)
{
    extern __shared__ char smem[];
    const uint32_t smem_b = smem_u32(smem);
    const int tid = threadIdx.x;
    const int wid = tid >> 5;
    const int lid = tid & 31;
    const int warp_m = wid >> 2;
    const int warp_n = wid & 3;
    const int bm = blockIdx.y * MBM;
    const int bn = blockIdx.x * MBN;
    const int K = 1024, N = 4096;

    const int g   = lid >> 2;
    const int tig = lid & 3;
    const int mat = lid >> 3;
    const int rwi = lid & 7;

    const int rowA_base = warp_m * 32 + rwi + (mat & 1) * 8;
    const int khA       = mat >> 1;
    const int rowB_base = warp_n * 32 + (mat >> 1) * 8 + rwi;
    const int khB       = mat & 1;

    float acc1[2][4][4], acc3[2][4][4];
#pragma unroll
    for (int i = 0; i < 2; ++i)
#pragma unroll
        for (int j = 0; j < 4; ++j)
#pragma unroll
            for (int q = 0; q < 4; ++q) { acc1[i][j][q] = 0.0f; acc3[i][j][q] = 0.0f; }

    const __nv_bfloat16* Ahb = Ah + (size_t)bm * K;
    const __nv_bfloat16* Alb = Al + (size_t)bm * K;
    const __nv_bfloat16* B1hb = B1h + (size_t)bn * K;
    const __nv_bfloat16* B1lb = B1l + (size_t)bn * K;
    const __nv_bfloat16* B3hb = B3h + (size_t)bn * K;
    const __nv_bfloat16* B3lb = B3l + (size_t)bn * K;
    const int nchunks = K / MBK;    // 16

    const int lrow_lo = tid >> 3;
    const int lch     = tid & 7;

    auto issue = [&](int kc, int stage) {
        const uint32_t sb2 = smem_b + stage * F_STAGE;
        const size_t koff = (size_t)kc * MBK + lch * 8;
#pragma unroll
        for (int i = 0; i < 12; ++i) {
            const int comp = i >> 1;
            const int row  = lrow_lo + (i & 1) * 64;
            const uint32_t sw16 = (uint32_t)(((lch ^ (row & 7)) << 4));
            uint32_t dst;
            const __nv_bfloat16* src;
            if (comp == 0)      { dst = sb2 + row * 256 + sw16;               src = Ahb  + (size_t)row * K + koff; }
            else if (comp == 1) { dst = sb2 + row * 256 + 128 + sw16;         src = Alb  + (size_t)row * K + koff; }
            else if (comp == 2) { dst = sb2 + 32768 + row * 256 + sw16;       src = B1hb + (size_t)row * K + koff; }
            else if (comp == 3) { dst = sb2 + 32768 + row * 256 + 128 + sw16; src = B1lb + (size_t)row * K + koff; }
            else if (comp == 4) { dst = sb2 + 65536 + row * 256 + sw16;       src = B3hb + (size_t)row * K + koff; }
            else                { dst = sb2 + 65536 + row * 256 + 128 + sw16; src = B3lb + (size_t)row * K + koff; }
            cp16(dst, src);
        }
        cp_commit();
    };

    issue(0, 0);

    int buf = 0;
    for (int c = 0; c < nchunks; ++c) {
        cp_wait0();
        __syncthreads();
        if (c + 1 < nchunks) issue(c + 1, buf ^ 1);   // safe: buf^1 done in c-1

        const uint32_t sa_u = smem_b + buf * F_STAGE;
#pragma unroll
        for (int ks = 0; ks < 4; ++ks) {
            uint32_t ah[2][4], al[2][4];
#pragma unroll
            for (int am = 0; am < 2; ++am) {
                int row = rowA_base + am * 16;
                uint32_t sw16 = (((2 * ks + khA) ^ (row & 7)) << 4);
                ldmx4(ah[am], sa_u + row * 256 + sw16);
                ldmx4(al[am], sa_u + row * 256 + 128 + sw16);
            }
            {   // w1 block
                uint32_t bh[2][4], bl[2][4];
                const uint32_t sbB = sa_u + 32768;
#pragma unroll
                for (int pr = 0; pr < 2; ++pr) {
                    int row = rowB_base + pr * 16;
                    uint32_t sw16 = (((2 * ks + khB) ^ (row & 7)) << 4);
                    ldmx4(bh[pr], sbB + row * 256 + sw16);
                    ldmx4(bl[pr], sbB + row * 256 + 128 + sw16);
                }
#pragma unroll
                for (int am = 0; am < 2; ++am)
#pragma unroll
                    for (int an = 0; an < 4; ++an)
                        mma16816(acc1[am][an], ah[am], &bh[an >> 1][(an & 1) * 2]);
#pragma unroll
                for (int am = 0; am < 2; ++am)
#pragma unroll
                    for (int an = 0; an < 4; ++an)
                        mma16816(acc1[am][an], ah[am], &bl[an >> 1][(an & 1) * 2]);
#pragma unroll
                for (int am = 0; am < 2; ++am)
#pragma unroll
                    for (int an = 0; an < 4; ++an)
                        mma16816(acc1[am][an], al[am], &bh[an >> 1][(an & 1) * 2]);
            }
            {   // w3 block
                uint32_t bh[2][4], bl[2][4];
                const uint32_t sbB = sa_u + 65536;
#pragma unroll
                for (int pr = 0; pr < 2; ++pr) {
                    int row = rowB_base + pr * 16;
                    uint32_t sw16 = (((2 * ks + khB) ^ (row & 7)) << 4);
                    ldmx4(bh[pr], sbB + row * 256 + sw16);
                    ldmx4(bl[pr], sbB + row * 256 + 128 + sw16);
                }
#pragma unroll
                for (int am = 0; am < 2; ++am)
#pragma unroll
                    for (int an = 0; an < 4; ++an)
                        mma16816(acc3[am][an], ah[am], &bh[an >> 1][(an & 1) * 2]);
#pragma unroll
                for (int am = 0; am < 2; ++am)
#pragma unroll
                    for (int an = 0; an < 4; ++an)
                        mma16816(acc3[am][an], ah[am], &bl[an >> 1][(an & 1) * 2]);
#pragma unroll
                for (int am = 0; am < 2; ++am)
#pragma unroll
                    for (int an = 0; an < 4; ++an)
                        mma16816(acc3[am][an], al[am], &bh[an >> 1][(an & 1) * 2]);
            }
        }
        buf ^= 1;
    }

    // epilogue: h = silu(acc1 + b1) * (acc3 + b3)
#pragma unroll
    for (int am = 0; am < 2; ++am) {
        const int row0 = bm + warp_m * 32 + am * 16 + g;
#pragma unroll
        for (int an = 0; an < 4; ++an) {
            const int col = bn + warp_n * 32 + an * 8 + tig * 2;
            float2 b1v = *(const float2*)(bias1 + col);
            float2 b3v = *(const float2*)(bias3 + col);
            const float* d1 = acc1[am][an];
            const float* d3 = acc3[am][an];
            const size_t p0 = (size_t)row0 * N + col;
            const size_t p1 = (size_t)(row0 + 8) * N + col;
            float h00 = siluf(d1[0] + b1v.x) * (d3[0] + b3v.x);
            float h01 = siluf(d1[1] + b1v.y) * (d3[1] + b3v.y);
            float h10 = siluf(d1[2] + b1v.x) * (d3[2] + b3v.x);
            float h11 = siluf(d1[3] + b1v.y) * (d3[3] + b3v.y);
            wr_hilo2(Oh, Ol, p0, h00, h01);
            wr_hilo2(Oh, Ol, p1, h10, h11);
        }
    }
}

// ---------------------------------------------------------------------------
// fp32 -> bf16 hi/lo conversion (weights, pos_emb)
// ---------------------------------------------------------------------------
__global__ __launch_bounds__(256)
void cvt_kernel(const float* __restrict__ src, __nv_bfloat16* __restrict__ hi,
                __nv_bfloat16* __restrict__ lo, int n4)
{
    int i = blockIdx.x * blockDim.x + threadIdx.x;
    if (i >= n4) return;
    float4 v = ((const float4*)src)[i];
    wr_hilo4(hi, lo, (size_t)i * 4, v);
}

// ---------------------------------------------------------------------------
// RMSNorm -> bf16 hi/lo (optionally sigmoid-gated blend of x and x_token)
// ---------------------------------------------------------------------------
__global__ __launch_bounds__(256)
void rms_kernel(const float* __restrict__ X, const float* __restrict__ XT,
                const float* __restrict__ lcw, const float* __restrict__ W,
                __nv_bfloat16* __restrict__ Oh, __nv_bfloat16* __restrict__ Ol,
                int gated)
{
    const int row = blockIdx.x;
    const int tid = threadIdx.x;
    float4 xv = ((const float4*)(X + (size_t)row * 1024))[tid];
    if (gated) {
        float lc = 1.0f / (1.0f + expf(-lcw[0]));
        float om = 1.0f - lc;
        float4 tv = ((const float4*)(XT + (size_t)row * 1024))[tid];
        xv.x = lc * xv.x + om * tv.x;
        xv.y = lc * xv.y + om * tv.y;
        xv.z = lc * xv.z + om * tv.z;
        xv.w = lc * xv.w + om * tv.w;
    }
    float ss = xv.x * xv.x + xv.y * xv.y + xv.z * xv.z + xv.w * xv.w;
#pragma unroll
    for (int o = 16; o > 0; o >>= 1) ss += __shfl_xor_sync(0xffffffffu, ss, o);
    __shared__ float red[8];
    if ((tid & 31) == 0) red[tid >> 5] = ss;
    __syncthreads();
    float tot = red[0] + red[1] + red[2] + red[3] + red[4] + red[5] + red[6] + red[7];
    float rinv = rsqrtf(tot * (1.0f / 1024.0f) + 1e-5f);
    float4 wv = ((const float4*)W)[tid];
    float4 ov;
    ov.x = xv.x * rinv * wv.x;
    ov.y = xv.y * rinv * wv.y;
    ov.z = xv.z * rinv * wv.z;
    ov.w = xv.w * rinv * wv.w;
    wr_hilo4(Oh, Ol, (size_t)row * 1024 + tid * 4, ov);
}

// ---------------------------------------------------------------------------
// Tensor-core causal flash attention (R15 version, known good).
// ---------------------------------------------------------------------------
#define AT_SMEM 98304

__global__ __launch_bounds__(128, 2)
void attn_mma(const __nv_bfloat16* __restrict__ Qh, const __nv_bfloat16* __restrict__ Ql,
              const __nv_bfloat16* __restrict__ Kh, const __nv_bfloat16* __restrict__ Kl,
              const __nv_bfloat16* __restrict__ Vh, const __nv_bfloat16* __restrict__ Vl,
              __nv_bfloat16* __restrict__ Oh, __nv_bfloat16* __restrict__ Ol)
{
    extern __shared__ char smem[];
    const uint32_t sb = smem_u32(smem);
    const int qt = blockIdx.x, h = blockIdx.y, b = blockIdx.z;
    const int q0 = qt * 128;
    const int tid = threadIdx.x;
    const int wid = tid >> 5;
    const int lid = tid & 31;
    const int g = lid >> 2, tig = lid & 3;
    const int mat = lid >> 3, rwi = lid & 7;
    const uint32_t AQ = sb, AK = sb + 32768, AV = sb + 49152, AP = sb + 65536;
    const float NEGINF = __int_as_float(0xff800000);

    {
        const int row = tid;
        const size_t gq = ((size_t)(b * 2048 + q0 + row)) * 1024 + h * 64;
#pragma unroll
        for (int cc = 0; cc < 8; ++cc) {
            const uint32_t sw = (uint32_t)(((cc ^ (row & 7)) << 4));
            cp16(AQ + row * 256 + sw,       Qh + gq + cc * 8);
            cp16(AQ + row * 256 + 128 + sw, Ql + gq + cc * 8);
        }
        cp_commit();
    }

    float oacc[2][8][4];
#pragma unroll
    for (int i = 0; i < 2; ++i)
#pragma unroll
        for (int j = 0; j < 8; ++j)
#pragma unroll
            for (int q = 0; q < 4; ++q) oacc[i][j][q] = 0.0f;
    float mrow[4], lrow[4];
#pragma unroll
    for (int i = 0; i < 4; ++i) { mrow[i] = NEGINF; lrow[i] = 0.0f; }

    const int ntiles = qt * 2 + 2;
    for (int t = 0; t < ntiles; ++t) {
        const int kt = t * 64;
        {
            const int row = tid >> 1;
            const int isv = tid & 1;
            const size_t gk = (size_t)(kt + row) * 1024 + h * 64;
            const size_t gv = ((size_t)(b * 2048 + kt + row)) * 1024 + h * 64;
            const __nv_bfloat16* sh = isv ? (Vh + gv) : (Kh + gk);
            const __nv_bfloat16* sl = isv ? (Vl + gv) : (Kl + gk);
            const uint32_t dstb = (isv ? AV : AK) + row * 256;
#pragma unroll
            for (int cc = 0; cc < 8; ++cc) {
                const uint32_t sw = (uint32_t)(((cc ^ (row & 7)) << 4));
                cp16(dstb + sw,       sh + cc * 8);
                cp16(dstb + 128 + sw, sl + cc * 8);
            }
            cp_commit();
        }
        cp_wait0();
        __syncthreads();

        float sacc[2][8][4];
#pragma unroll
        for (int i = 0; i < 2; ++i)
#pragma unroll
            for (int j = 0; j < 8; ++j)
#pragma unroll
                for (int q = 0; q < 4; ++q) sacc[i][j][q] = 0.0f;
#pragma unroll
        for (int ks = 0; ks < 4; ++ks) {
            uint32_t qh2[2][4], ql2[2][4], kh2[4][4], kl2[4][4];
#pragma unroll
            for (int am = 0; am < 2; ++am) {
                const int row = wid * 32 + am * 16 + rwi + (mat & 1) * 8;
                const uint32_t sw = (uint32_t)((((2 * ks + (mat >> 1)) ^ (row & 7)) << 4));
                ldmx4(qh2[am], AQ + row * 256 + sw);
                ldmx4(ql2[am], AQ + row * 256 + 128 + sw);
            }
#pragma unroll
            for (int pr = 0; pr < 4; ++pr) {
                const int row = pr * 16 + (mat >> 1) * 8 + rwi;
                const uint32_t sw = (uint32_t)((((2 * ks + (mat & 1)) ^ (row & 7)) << 4));
                ldmx4(kh2[pr], AK + row * 256 + sw);
                ldmx4(kl2[pr], AK + row * 256 + 128 + sw);
            }
#pragma unroll
            for (int am = 0; am < 2; ++am)
#pragma unroll
                for (int an = 0; an < 8; ++an)
                    mma16816(sacc[am][an], qh2[am], &kh2[an >> 1][(an & 1) * 2]);
#pragma unroll
            for (int am = 0; am < 2; ++am)
#pragma unroll
                for (int an = 0; an < 8; ++an)
                    mma16816(sacc[am][an], qh2[am], &kl2[an >> 1][(an & 1) * 2]);
#pragma unroll
            for (int am = 0; am < 2; ++am)
#pragma unroll
                for (int an = 0; an < 8; ++an)
                    mma16816(sacc[am][an], ql2[am], &kh2[an >> 1][(an & 1) * 2]);
        }

        const bool need_mask = (kt + 63 > q0 + wid * 32);
#pragma unroll
        for (int rs = 0; rs < 4; ++rs) {
            const int am = rs >> 1, hh = rs & 1;
            const int prow = wid * 32 + am * 16 + g + 8 * hh;
            const int row_g = q0 + prow;
            float v16[16];
#pragma unroll
            for (int an = 0; an < 8; ++an) {
                v16[an * 2]     = sacc[am][an][hh * 2];
                v16[an * 2 + 1] = sacc[am][an][hh * 2 + 1];
            }
            if (need_mask) {
#pragma unroll
                for (int an = 0; an < 8; ++an) {
                    const int c0 = kt + an * 8 + tig * 2;
                    if (c0 > row_g)     v16[an * 2]     = NEGINF;
                    if (c0 + 1 > row_g) v16[an * 2 + 1] = NEGINF;
                }
            }
            float rmax = v16[0];
#pragma unroll
            for (int i = 1; i < 16; ++i) rmax = fmaxf(rmax, v16[i]);
            rmax = fmaxf(rmax, __shfl_xor_sync(0xffffffffu, rmax, 1));
            rmax = fmaxf(rmax, __shfl_xor_sync(0xffffffffu, rmax, 2));
            const float mn = fmaxf(mrow[rs], rmax);
            const float f = __expf(mrow[rs] - mn);
            mrow[rs] = mn;
            float sum = 0.0f;
#pragma unroll
            for (int i = 0; i < 16; ++i) { v16[i] = __expf(v16[i] - mn); sum += v16[i]; }
            sum += __shfl_xor_sync(0xffffffffu, sum, 1);
            sum += __shfl_xor_sync(0xffffffffu, sum, 2);
            lrow[rs] = lrow[rs] * f + sum;
#pragma unroll
            for (int an = 0; an < 8; ++an) {
                oacc[am][an][hh * 2]     *= f;
                oacc[am][an][hh * 2 + 1] *= f;
            }
            const uint32_t pb = AP + prow * 256 + tig * 4;
#pragma unroll
            for (int an = 0; an < 8; ++an) {
                const uint32_t sw = (uint32_t)(((an ^ (prow & 7)) << 4));
                float a = v16[an * 2], b2 = v16[an * 2 + 1];
                __nv_bfloat16 ha = __float2bfloat16(a), hb = __float2bfloat16(b2);
                __nv_bfloat16 la = __float2bfloat16(a - __bfloat162float(ha));
                __nv_bfloat16 lb = __float2bfloat16(b2 - __bfloat162float(hb));
                uint32_t hw = (uint32_t)__bfloat16_as_ushort(ha) |
                              ((uint32_t)__bfloat16_as_ushort(hb) << 16);
                uint32_t lw = (uint32_t)__bfloat16_as_ushort(la) |
                              ((uint32_t)__bfloat16_as_ushort(lb) << 16);
                asm volatile("st.shared.b32 [%0], %1;" :: "r"(pb + sw), "r"(hw));
                asm volatile("st.shared.b32 [%0], %1;" :: "r"(pb + 128 + sw), "r"(lw));
            }
        }
        __syncwarp();

#pragma unroll
        for (int ks = 0; ks < 4; ++ks) {
            uint32_t ph2[2][4], pl2[2][4], vh2[4][4], vl2[4][4];
#pragma unroll
            for (int am = 0; am < 2; ++am) {
                const int row = wid * 32 + am * 16 + rwi + (mat & 1) * 8;
                const uint32_t sw = (uint32_t)((((2 * ks + (mat >> 1)) ^ (row & 7)) << 4));
                ldmx4(ph2[am], AP + row * 256 + sw);
                ldmx4(pl2[am], AP + row * 256 + 128 + sw);
            }
#pragma unroll
            for (int pr = 0; pr < 4; ++pr) {
                const int row = ks * 16 + (mat & 1) * 8 + rwi;
                const uint32_t sw = (uint32_t)((((pr * 2 + (mat >> 1)) ^ (row & 7)) << 4));
                ldmx4t(vh2[pr], AV + row * 256 + sw);
                ldmx4t(vl2[pr], AV + row * 256 + 128 + sw);
            }
#pragma unroll
            for (int am = 0; am < 2; ++am)
#pragma unroll
                for (int an = 0; an < 8; ++an)
                    mma16816(oacc[am][an], ph2[am], &vh2[an >> 1][(an & 1) * 2]);
#pragma unroll
            for (int am = 0; am < 2; ++am)
#pragma unroll
                for (int an = 0; an < 8; ++an)
                    mma16816(oacc[am][an], ph2[am], &vl2[an >> 1][(an & 1) * 2]);
#pragma unroll
            for (int am = 0; am < 2; ++am)
#pragma unroll
                for (int an = 0; an < 8; ++an)
                    mma16816(oacc[am][an], pl2[am], &vh2[an >> 1][(an & 1) * 2]);
        }
        __syncthreads();
    }

#pragma unroll
    for (int rs = 0; rs < 4; ++rs) {
        const int am = rs >> 1, hh = rs & 1;
        const int prow = wid * 32 + am * 16 + g + 8 * hh;
        const float inv = 1.0f / lrow[rs];
        const size_t gb = ((size_t)(b * 2048 + q0 + prow)) * 1024 + h * 64;
#pragma unroll
        for (int an = 0; an < 8; ++an) {
            const int col = an * 8 + tig * 2;
            wr_hilo2(Oh, Ol, gb + col,
                     oacc[am][an][hh * 2] * inv, oacc[am][an][hh * 2 + 1] * inv);
        }
    }
}

// ---------------------------------------------------------------------------
// Launch
// ---------------------------------------------------------------------------
extern "C" void kernel_launch(void* const* d_in, const int* in_sizes, int n_in,
                              void* d_out, int out_size)
{
    const float* x       = (const float*)d_in[0];
    const float* x_token = (const float*)d_in[1];
    const float* pos_emb = (const float*)d_in[2];
    const float* lcw     = (const float*)d_in[3];
    const float* Wq      = (const float*)d_in[4];
    const float* Wk      = (const float*)d_in[5];
    const float* Wv      = (const float*)d_in[6];
    const float* proj_w  = (const float*)d_in[7];
    const float* proj_b  = (const float*)d_in[8];
    const float* w1_w    = (const float*)d_in[9];
    const float* w1_b    = (const float*)d_in[10];
    const float* w2_w    = (const float*)d_in[11];
    const float* w2_b    = (const float*)d_in[12];
    const float* w3_w    = (const float*)d_in[13];
    const float* w3_b    = (const float*)d_in[14];
    const float* n1w     = (const float*)d_in[15];
    const float* n2w     = (const float*)d_in[16];
    float* out = (float*)d_out;

    float *xm;
    __nv_bfloat16* bf;
    cudaGetSymbolAddress((void**)&xm, g_xm);
    cudaGetSymbolAddress((void**)&bf, g_bf);

    __nv_bfloat16 *wq_h = bf + O_WQ, *wq_l = wq_h + SZ_1M;
    __nv_bfloat16 *wk_h = bf + O_WK, *wk_l = wk_h + SZ_1M;
    __nv_bfloat16 *wv_h = bf + O_WV, *wv_l = wv_h + SZ_1M;
    __nv_bfloat16 *pw_h = bf + O_PW, *pw_l = pw_h + SZ_1M;
    __nv_bfloat16 *w1h  = bf + O_W1, *w1l  = w1h + SZ_4M;
    __nv_bfloat16 *w2h  = bf + O_W2, *w2l  = w2h + SZ_4M;
    __nv_bfloat16 *w3h  = bf + O_W3, *w3l  = w3h + SZ_4M;
    __nv_bfloat16 *pe_h = bf + O_PE, *pe_l = pe_h + SZ_2M;
    __nv_bfloat16 *xn_h = bf + O_XN, *xn_l = xn_h + SZ_4M;
    __nv_bfloat16 *at_h = bf + O_AT, *at_l = at_h + SZ_4M;
    __nv_bfloat16 *h_h  = bf + O_H,  *h_l  = h_h + SZ_16M;
    __nv_bfloat16 *q_h  = bf + O_QB, *q_l  = q_h + SZ_4M;
    __nv_bfloat16 *k_h  = bf + O_KB, *k_l  = k_h + SZ_2M;
    __nv_bfloat16 *v_h  = bf + O_VB, *v_l  = v_h + SZ_4M;

    cudaFuncSetAttribute(mma_gemm<1>, cudaFuncAttributeMaxDynamicSharedMemorySize, MM_SMEM);
    cudaFuncSetAttribute(qkv_gemm,    cudaFuncAttributeMaxDynamicSharedMemorySize, MM_SMEM);
    cudaFuncSetAttribute(ffn_gemm,    cudaFuncAttributeMaxDynamicSharedMemorySize, FF_SMEM);
    cudaFuncSetAttribute(attn_mma,    cudaFuncAttributeMaxDynamicSharedMemorySize, AT_SMEM);

    // 0) convert weights + pos_emb to bf16 hi/lo
    cvt_kernel<<<SZ_1M / 4 / 256, 256>>>(Wq,      wq_h, wq_l, SZ_1M / 4);
    cvt_kernel<<<SZ_1M / 4 / 256, 256>>>(Wk,      wk_h, wk_l, SZ_1M / 4);
    cvt_kernel<<<SZ_1M / 4 / 256, 256>>>(Wv,      wv_h, wv_l, SZ_1M / 4);
    cvt_kernel<<<SZ_1M / 4 / 256, 256>>>(proj_w,  pw_h, pw_l, SZ_1M / 4);
    cvt_kernel<<<SZ_4M / 4 / 256, 256>>>(w1_w,    w1h,  w1l,  SZ_4M / 4);
    cvt_kernel<<<SZ_4M / 4 / 256, 256>>>(w2_w,    w2h,  w2l,  SZ_4M / 4);
    cvt_kernel<<<SZ_4M / 4 / 256, 256>>>(w3_w,    w3h,  w3l,  SZ_4M / 4);
    cvt_kernel<<<SZ_2M / 4 / 256, 256>>>(pos_emb, pe_h, pe_l, SZ_2M / 4);

    // 1) gated rmsnorm -> xn (bf16 hi/lo)
    rms_kernel<<<4096, 256>>>(x, x_token, lcw, n1w, xn_h, xn_l, 1);
    // 2) fused q/k/v projections
    QKVArgs qa;
    qa.xnh = xn_h; qa.xnl = xn_l; qa.peh = pe_h; qa.pel = pe_l;
    qa.wqh = wq_h; qa.wql = wq_l; qa.wkh = wk_h; qa.wkl = wk_l;
    qa.wvh = wv_h; qa.wvl = wv_l;
    qa.qh = q_h; qa.ql = q_l; qa.kh = k_h; qa.kl = k_l; qa.vh = v_h; qa.vl = v_l;
    qkv_gemm<<<dim3(8, 32, 3), 512, MM_SMEM>>>(qa);
    // 3) tensor-core causal attention -> at (bf16 hi/lo)
    attn_mma<<<dim3(16, 16, 2), 128, AT_SMEM>>>(q_h, q_l, k_h, k_l, v_h, v_l, at_h, at_l);
    // 4) x_mid = x + attn @ proj_w^T + proj_b  (fp32)
    mma_gemm<1><<<dim3(8, 32), 512, MM_SMEM>>>(at_h, at_l, pw_h, pw_l, proj_b, x, xm, nullptr, nullptr, 4096, 1024, 1024, 1.0f);
    // 5) xn2 = rmsnorm(x_mid) -> xn (bf16 hi/lo)
    rms_kernel<<<4096, 256>>>(xm, nullptr, nullptr, n2w, xn_h, xn_l, 0);
    // 6) fused FFN-up: h = silu(xn@W1^T+b1) * (xn@W3^T+b3) -> bf16 hi/lo
    ffn_gemm<<<dim3(32, 32), 512, FF_SMEM>>>(xn_h, xn_l, w1h, w1l, w3h, w3l,
                                             w1_b, w3_b, h_h, h_l);
    // 7) out = x_mid + h @ w2^T + b2  (fp32)
    mma_gemm<1><<<dim3(8, 32), 512, MM_SMEM>>>(h_h, h_l, w2h, w2l, w2_b, xm, out, nullptr, nullptr, 4096, 1024, 4096, 1.0f);
}